// round 9
// baseline (speedup 1.0000x reference)
#include <cuda_runtime.h>
#include <math.h>

#define NPIX 16384
#define BN   65536   // 4 * 16384
#define NPAIR 32768  // BN/2

typedef unsigned long long u64;

// ------------ scratch ------------------------------------------------------
__device__ float g_k[64*BN];
__device__ float g_q[64*BN];
__device__ u64   g_vP[32*BN];       // v packed (e,e+1)
__device__ u64   g_xmP[32*BN];      // xm packed (c,c+1)
__device__ u64   g_uA[64*BN];       // layer1 u staging, packed (o,o+1)
__device__ u64   g_uB[128*NPAIR];   // layer2 partials, packed (px0,px1)
__device__ u64   g_uC[64*BN];       // layer2 u staging, packed (o,o+1)
__device__ float g_Gpart[4*128*1024];
__device__ float g_sqp[4*128*64];
__device__ float g_skp[4*128*64];
__device__ float g_weffT[4*4096];
__device__ float g_wcatT[4096];
__device__ float g_wikT[4096];
__device__ float g_wivT[4096];
__device__ float g_wqT[4096];
__device__ float g_w1T[8192];
__device__ float g_w2T[16384];
__device__ float g_bcat[64];
__device__ float g_bik[64];
__device__ float g_biv[64];

// ------------ f32x2 helpers --------------------------------------------------
__device__ __forceinline__ u64 pack2(float lo, float hi){
    u64 r; asm("mov.b64 %0, {%1,%2};" : "=l"(r) : "f"(lo), "f"(hi)); return r;
}
__device__ __forceinline__ void unpack2(u64 a, float& lo, float& hi){
    asm("mov.b64 {%0,%1}, %2;" : "=f"(lo), "=f"(hi) : "l"(a));
}
__device__ __forceinline__ u64 fma2_(u64 a, u64 b, u64 c){
    u64 d; asm("fma.rn.f32x2 %0, %1, %2, %3;" : "=l"(d) : "l"(a), "l"(b), "l"(c)); return d;
}
__device__ __forceinline__ u64 add2_(u64 a, u64 b){
    u64 d; asm("add.rn.f32x2 %0, %1, %2;" : "=l"(d) : "l"(a), "l"(b)); return d;
}
__device__ __forceinline__ float hadd2(u64 a){
    float lo, hi; unpack2(a, lo, hi); return lo + hi;
}

// single-pixel 64-dot (16 LDS : 32 FMA2)
__device__ __forceinline__ float dot64p(const float* w, const u64* xp){
    const ulonglong2* w2 = (const ulonglong2*)w;
    u64 a0=0ull,a1=0ull,a2=0ull,a3=0ull;
    #pragma unroll
    for (int i=0;i<8;i++){
        ulonglong2 wa=w2[2*i], wb=w2[2*i+1];
        a0=fma2_(xp[4*i+0], wa.x, a0);
        a1=fma2_(xp[4*i+1], wa.y, a1);
        a2=fma2_(xp[4*i+2], wb.x, a2);
        a3=fma2_(xp[4*i+3], wb.y, a3);
    }
    return hadd2(add2_(add2_(a0,a1),add2_(a2,a3)));
}
// dual-pixel 64-dot: one weight-row load serves two pixels (16 LDS : 64 FMA2)
__device__ __forceinline__ void dot64p_dual(const float* w, const u64* xa, const u64* xb,
                                            float& ra, float& rb){
    const ulonglong2* w2 = (const ulonglong2*)w;
    u64 aa0=0ull,aa1=0ull,ba0=0ull,ba1=0ull;
    #pragma unroll
    for (int i=0;i<16;i++){
        ulonglong2 wv=w2[i];
        aa0=fma2_(xa[2*i],   wv.x, aa0);
        aa1=fma2_(xa[2*i+1], wv.y, aa1);
        ba0=fma2_(xb[2*i],   wv.x, ba0);
        ba1=fma2_(xb[2*i+1], wv.y, ba1);
    }
    ra = hadd2(add2_(aa0,aa1));
    rb = hadd2(add2_(ba0,ba1));
}

// ------------ kprep: fold + transpose weights -------------------------------
__global__ void kprep(const float* wa, const float* ba, const float* wb, const float* bb,
                      const float* wq, const float* w1, const float* w2)
{
    int t = blockIdx.x*256 + threadIdx.x;     // 0..16383
    if (t < 4096) {
        int j = t>>6, c = t&63;
        float w;
        if (j < 4) w = wa[c*4 + j];
        else { int u=j-4; int kk=u/3; int d=u-kk*3; w = wb[kk*192 + c*3 + d]; }
        g_wcatT[t] = w;
        g_wqT[t]   = wq[c*64 + j];
    }
    if (t < 8192)  { int o=t>>6, c=t&63;  g_w1T[t] = w1[c*128 + o]; }
    if (t < 16384) { int o=t>>7, i=t&127; g_w2T[t] = w2[i*128 + o]; }
    if (t < 64) g_bcat[t] = (t < 4) ? ba[t] : bb[t-4];
}

__global__ void kfold(const float* inw, const float* inb,
                      const float* wk, const float* bk,
                      const float* wv, const float* bv)
{
    int t = blockIdx.x*256 + threadIdx.x;     // 0..8191
    int o = (t>>6)&63, c = t&63;
    const float* wx = (t < 4096) ? wk : wv;
    float acc = 0.f;
    #pragma unroll 4
    for (int m=0;m<64;m++) acc = fmaf(inw[c*64+m], wx[m*64+o], acc);
    if (t < 4096) g_wikT[o*64+c] = acc;
    else          g_wivT[o*64+c] = acc;
    if (t < 64) {
        float a=0.f, b2=0.f;
        for (int m=0;m<64;m++){ a=fmaf(inb[m],wk[m*64+t],a); b2=fmaf(inb[m],wv[m*64+t],b2); }
        g_bik[t] = a + bk[t];
        g_biv[t] = b2 + bv[t];
    }
}

// ------------ k1: feat path -> k, v  (2 px/thread) ---------------------------
// dyn smem floats: s_w 12288 | s_sem 10752 | s_bias 192 = 23232 f
__global__ void __launch_bounds__(256,1)
k1(const float* __restrict__ x, const float* __restrict__ sem)
{
    extern __shared__ float smx[];
    float* s_w    = smx;            // wcatT | wikT | wivT
    float* s_sem  = smx + 12288;    // 21*512
    float* s_bias = smx + 23040;    // 192
    int t = threadIdx.x;
    int gp0 = blockIdx.x*512 + t, gp1 = gp0 + 256;
    int b = gp0 >> 14, p0 = gp0 & (NPIX-1), p1 = p0 + 256;

    for (int i=t;i<4096;i+=256){
        s_w[i]      = g_wcatT[i];
        s_w[4096+i] = g_wikT[i];
        s_w[8192+i] = g_wivT[i];
    }
    if (t<64){ s_bias[t]=g_bcat[t]; s_bias[64+t]=g_bik[t]; s_bias[128+t]=g_biv[t]; }
    int sbase = b*21*NPIX;
    #pragma unroll
    for (int kk=0;kk<21;kk++){
        float s0=sem[sbase+kk*NPIX+p0], s1=sem[sbase+kk*NPIX+p1];
        s_sem[kk*512+t]     = s0>0.f?s0:0.f;
        s_sem[kk*512+256+t] = s1>0.f?s1:0.f;
    }
    int xbase = b*64*NPIX;
    u64 xp[32];
    #pragma unroll
    for (int c=0;c<64;c+=2) xp[c>>1]=pack2(x[xbase+c*NPIX+p0], x[xbase+(c+1)*NPIX+p0]);
    __syncthreads();

    // all_feat px0
    u64 ap0[32];
    #pragma unroll 2
    for (int j=0;j<64;j+=2){
        float d0 = dot64p(s_w + j*64, xp);
        float d1 = dot64p(s_w + (j+1)*64, xp);
        int cls0 = (j   < 4) ? 0 : ((j-4)/3 + 1);
        int cls1 = (j+1 < 4) ? 0 : ((j-3)/3 + 1);
        ap0[j>>1] = pack2(s_sem[cls0*512+t]*d0 + s_bias[j],
                          s_sem[cls1*512+t]*d1 + s_bias[j+1]);
    }
    // all_feat px1
    #pragma unroll
    for (int c=0;c<64;c+=2) xp[c>>1]=pack2(x[xbase+c*NPIX+p1], x[xbase+(c+1)*NPIX+p1]);
    u64 ap1[32];
    #pragma unroll 2
    for (int j=0;j<64;j+=2){
        float d0 = dot64p(s_w + j*64, xp);
        float d1 = dot64p(s_w + (j+1)*64, xp);
        int cls0 = (j   < 4) ? 0 : ((j-4)/3 + 1);
        int cls1 = (j+1 < 4) ? 0 : ((j-3)/3 + 1);
        ap1[j>>1] = pack2(s_sem[cls0*512+256+t]*d0 + s_bias[j],
                          s_sem[cls1*512+256+t]*d1 + s_bias[j+1]);
    }
    // k (dual rows)
    #pragma unroll 2
    for (int o=0;o<64;o++){
        float r0,r1; dot64p_dual(s_w + 4096 + o*64, ap0, ap1, r0, r1);
        g_k[o*BN+gp0] = r0 + s_bias[64+o];
        g_k[o*BN+gp1] = r1 + s_bias[64+o];
    }
    // v (dual rows, packed output)
    #pragma unroll 2
    for (int o=0;o<64;o+=2){
        float v00,v10; dot64p_dual(s_w + 8192 + o*64, ap0, ap1, v00, v10);
        float v01,v11; dot64p_dual(s_w + 8192 + (o+1)*64, ap0, ap1, v01, v11);
        g_vP[(o>>1)*BN+gp0] = pack2(v00 + s_bias[128+o], v01 + s_bias[129+o]);
        g_vP[(o>>1)*BN+gp1] = pack2(v10 + s_bias[128+o], v11 + s_bias[129+o]);
    }
}

// ------------ k2: LN-MLP -> xm, q  (2 px/thread, split-K layer2) -------------
// dyn smem floats: wbuf 8192 | s_p 896 = 9088 f
__global__ void __launch_bounds__(256,1)
k2(const float* __restrict__ x,
   const float* __restrict__ b1, const float* __restrict__ gm1, const float* __restrict__ be1,
   const float* __restrict__ b2, const float* __restrict__ gm2, const float* __restrict__ be2,
   const float* __restrict__ w3, const float* __restrict__ b3, const float* __restrict__ bq)
{
    extern __shared__ float smx[];
    float* wbuf = smx;            // 8192
    float* s_p  = smx + 8192;     // 896
    int t = threadIdx.x;
    int gp0 = blockIdx.x*512 + t, gp1 = gp0 + 256;
    int pidx = blockIdx.x*256 + t;
    int b = gp0 >> 14, p0 = gp0 & (NPIX-1), p1 = p0 + 256;

    if (t < 128){
        s_p[t]=b1[t]; s_p[128+t]=gm1[t]; s_p[256+t]=be1[t];
        s_p[384+t]=b2[t]; s_p[512+t]=gm2[t]; s_p[640+t]=be2[t];
    }
    if (t<64){ s_p[768+t]=b3[t]; s_p[832+t]=bq[t]; }
    for (int i=t;i<8192;i+=256) wbuf[i]=g_w1T[i];

    int xbase = b*64*NPIX;
    u64 xp0[32], xp1[32];
    #pragma unroll
    for (int c=0;c<64;c+=2){
        xp0[c>>1]=pack2(x[xbase+c*NPIX+p0], x[xbase+(c+1)*NPIX+p0]);
        xp1[c>>1]=pack2(x[xbase+c*NPIX+p1], x[xbase+(c+1)*NPIX+p1]);
    }
    __syncthreads();

    // ---- layer 1 (paired), u staged to g_uA ----
    u64 sA=0ull,s2A=0ull,sB=0ull,s2B=0ull;
    #pragma unroll 2
    for (int o=0;o<128;o+=2){
        float u00,u10; dot64p_dual(wbuf + o*64,     xp0, xp1, u00, u10);
        float u01,u11; dot64p_dual(wbuf + (o+1)*64, xp0, xp1, u01, u11);
        u00+=s_p[o]; u01+=s_p[o+1]; u10+=s_p[o]; u11+=s_p[o+1];
        u64 ua=pack2(u00,u01), ub=pack2(u10,u11);
        g_uA[(o>>1)*BN+gp0]=ua; g_uA[(o>>1)*BN+gp1]=ub;
        sA=add2_(sA,ua); s2A=fma2_(ua,ua,s2A);
        sB=add2_(sB,ub); s2B=fma2_(ub,ub,s2B);
    }
    float m0,ri0,m1,ri1;
    { float s=hadd2(sA), s2=hadd2(s2A); m0=s*(1.f/128.f);
      float v=s2*(1.f/128.f)-m0*m0; ri0=rsqrtf(v+1e-5f); }
    { float s=hadd2(sB), s2=hadd2(s2B); m1=s*(1.f/128.f);
      float v=s2*(1.f/128.f)-m1*m1; ri1=rsqrtf(v+1e-5f); }

    // ---- layer 2 half A ----
    __syncthreads();
    for (int i=t;i<8192;i+=256){ int o=i>>6, ih=i&63; wbuf[i]=g_w2T[o*128+ih]; }
    u64 h0[32], h1[32];
    #pragma unroll 4
    for (int ip=0; ip<32; ip++){
        float ua,ub; unpack2(g_uA[ip*BN+gp0], ua, ub);
        float v0=(ua-m0)*ri0*s_p[128+2*ip]+s_p[256+2*ip];
        float v1=(ub-m0)*ri0*s_p[128+2*ip+1]+s_p[256+2*ip+1];
        v0 = v0>0.f?v0:0.01f*v0;  v1 = v1>0.f?v1:0.01f*v1;
        h0[ip]=pack2(v0,v1);
        unpack2(g_uA[ip*BN+gp1], ua, ub);
        v0=(ua-m1)*ri1*s_p[128+2*ip]+s_p[256+2*ip];
        v1=(ub-m1)*ri1*s_p[128+2*ip+1]+s_p[256+2*ip+1];
        v0 = v0>0.f?v0:0.01f*v0;  v1 = v1>0.f?v1:0.01f*v1;
        h1[ip]=pack2(v0,v1);
    }
    __syncthreads();
    #pragma unroll 2
    for (int o=0;o<128;o++){
        float pa0,pa1; dot64p_dual(wbuf + o*64, h0, h1, pa0, pa1);
        g_uB[o*NPAIR + pidx] = pack2(pa0, pa1);
    }

    // ---- layer 2 half B ----
    __syncthreads();
    for (int i=t;i<8192;i+=256){ int o=i>>6, ih=i&63; wbuf[i]=g_w2T[o*128+64+ih]; }
    #pragma unroll 4
    for (int ip=32; ip<64; ip++){
        float ua,ub; unpack2(g_uA[ip*BN+gp0], ua, ub);
        float v0=(ua-m0)*ri0*s_p[128+2*ip]+s_p[256+2*ip];
        float v1=(ub-m0)*ri0*s_p[128+2*ip+1]+s_p[256+2*ip+1];
        v0 = v0>0.f?v0:0.01f*v0;  v1 = v1>0.f?v1:0.01f*v1;
        h0[ip-32]=pack2(v0,v1);
        unpack2(g_uA[ip*BN+gp1], ua, ub);
        v0=(ua-m1)*ri1*s_p[128+2*ip]+s_p[256+2*ip];
        v1=(ub-m1)*ri1*s_p[128+2*ip+1]+s_p[256+2*ip+1];
        v0 = v0>0.f?v0:0.01f*v0;  v1 = v1>0.f?v1:0.01f*v1;
        h1[ip-32]=pack2(v0,v1);
    }
    __syncthreads();
    sA=0ull;s2A=0ull;sB=0ull;s2B=0ull;
    #pragma unroll 2
    for (int o=0;o<128;o+=2){
        float q00,q10; dot64p_dual(wbuf + o*64,     h0, h1, q00, q10);
        float q01,q11; dot64p_dual(wbuf + (o+1)*64, h0, h1, q01, q11);
        float pa0,pa1; unpack2(g_uB[o*NPAIR+pidx], pa0, pa1);
        float pb0,pb1; unpack2(g_uB[(o+1)*NPAIR+pidx], pb0, pb1);
        float u00=q00+pa0+s_p[384+o], u01=q01+pb0+s_p[384+o+1];
        float u10=q10+pa1+s_p[384+o], u11=q11+pb1+s_p[384+o+1];
        u64 ua=pack2(u00,u01), ub=pack2(u10,u11);
        g_uC[(o>>1)*BN+gp0]=ua; g_uC[(o>>1)*BN+gp1]=ub;
        sA=add2_(sA,ua); s2A=fma2_(ua,ua,s2A);
        sB=add2_(sB,ub); s2B=fma2_(ub,ub,s2B);
    }
    { float s=hadd2(sA), s2=hadd2(s2A); m0=s*(1.f/128.f);
      float v=s2*(1.f/128.f)-m0*m0; ri0=rsqrtf(v+1e-5f); }
    { float s=hadd2(sB), s2=hadd2(s2B); m1=s*(1.f/128.f);
      float v=s2*(1.f/128.f)-m1*m1; ri1=rsqrtf(v+1e-5f); }

    // ---- layer 3: rank-1 paired ----
    __syncthreads();
    for (int i=t;i<8192;i+=256) wbuf[i]=w3[i];
    __syncthreads();
    u64 xm0[32], xm1[32];
    #pragma unroll
    for (int c=0;c<64;c+=2){
        u64 bb = pack2(s_p[768+c], s_p[768+c+1]);
        xm0[c>>1]=bb; xm1[c>>1]=bb;
    }
    #pragma unroll 2
    for (int ip=0; ip<64; ip++){
        int i0 = 2*ip;
        float ua,ub; unpack2(g_uC[ip*BN+gp0], ua, ub);
        float v00=(ua-m0)*ri0*s_p[512+i0]+s_p[640+i0];
        float v01=(ub-m0)*ri0*s_p[512+i0+1]+s_p[640+i0+1];
        v00 = v00>0.f?v00:0.01f*v00;  v01 = v01>0.f?v01:0.01f*v01;
        unpack2(g_uC[ip*BN+gp1], ua, ub);
        float v10=(ua-m1)*ri1*s_p[512+i0]+s_p[640+i0];
        float v11=(ub-m1)*ri1*s_p[512+i0+1]+s_p[640+i0+1];
        v10 = v10>0.f?v10:0.01f*v10;  v11 = v11>0.f?v11:0.01f*v11;
        u64 vv00=pack2(v00,v00), vv01=pack2(v01,v01);
        u64 vv10=pack2(v10,v10), vv11=pack2(v11,v11);
        const ulonglong2* r0=(const ulonglong2*)(wbuf + i0*64);
        const ulonglong2* r1=(const ulonglong2*)(wbuf + (i0+1)*64);
        #pragma unroll
        for (int c2=0;c2<16;c2++){
            ulonglong2 wa=r0[c2], wb=r1[c2];
            xm0[2*c2]   = fma2_(vv00, wa.x, xm0[2*c2]);
            xm0[2*c2+1] = fma2_(vv00, wa.y, xm0[2*c2+1]);
            xm0[2*c2]   = fma2_(vv01, wb.x, xm0[2*c2]);
            xm0[2*c2+1] = fma2_(vv01, wb.y, xm0[2*c2+1]);
            xm1[2*c2]   = fma2_(vv10, wa.x, xm1[2*c2]);
            xm1[2*c2+1] = fma2_(vv10, wa.y, xm1[2*c2+1]);
            xm1[2*c2]   = fma2_(vv11, wb.x, xm1[2*c2]);
            xm1[2*c2+1] = fma2_(vv11, wb.y, xm1[2*c2+1]);
        }
    }
    #pragma unroll
    for (int c2=0;c2<32;c2++){
        g_xmP[c2*BN+gp0]=xm0[c2];
        g_xmP[c2*BN+gp1]=xm1[c2];
    }
    // ---- q (paired) ----
    __syncthreads();
    for (int i=t;i<4096;i+=256) wbuf[i]=g_wqT[i];
    __syncthreads();
    #pragma unroll 2
    for (int j=0;j<64;j++){
        float q0,q1; dot64p_dual(wbuf + j*64, xm0, xm1, q0, q1);
        g_q[j*BN+gp0]=q0+s_p[832+j];
        g_q[j*BN+gp1]=q1+s_p[832+j];
    }
}

// ------------ k3: Gram + norm partials per 128-pixel chunk -------------------
#define CHUNK 128
#define TP 129
__global__ void __launch_bounds__(256,2) k3()
{
    extern __shared__ float smx[];
    float* qs  = smx;
    float* ks  = smx + 64*TP;
    float* red = smx + 128*TP;
    int t = threadIdx.x;
    int chunk = blockIdx.x, b = blockIdx.y;
    int pbase = b*NPIX + chunk*CHUNK;
    for (int i=t; i<64*CHUNK; i+=256){
        int ch=i>>7, pp=i&(CHUNK-1);
        qs[ch*TP+pp]=g_q[ch*BN+pbase+pp];
        ks[ch*TP+pp]=g_k[ch*BN+pbase+pp];
    }
    __syncthreads();
    int sub=t>>6, combo=t&63;
    int h=combo>>4, d4=(combo>>2)&3, e4=combo&3;
    const float* qsb=qs+(h*16+d4*4)*TP;
    const float* ksb=ks+(h*16+e4*4)*TP;
    float acc[4][4];
    #pragma unroll
    for (int i=0;i<4;i++)
        #pragma unroll
        for (int j=0;j<4;j++) acc[i][j]=0.f;
    for (int pp=sub*32; pp<sub*32+32; pp++){
        float q0=qsb[pp],q1=qsb[TP+pp],q2=qsb[2*TP+pp],q3=qsb[3*TP+pp];
        float k0=ksb[pp],k1v=ksb[TP+pp],k2v=ksb[2*TP+pp],k3v=ksb[3*TP+pp];
        acc[0][0]=fmaf(q0,k0,acc[0][0]); acc[0][1]=fmaf(q0,k1v,acc[0][1]); acc[0][2]=fmaf(q0,k2v,acc[0][2]); acc[0][3]=fmaf(q0,k3v,acc[0][3]);
        acc[1][0]=fmaf(q1,k0,acc[1][0]); acc[1][1]=fmaf(q1,k1v,acc[1][1]); acc[1][2]=fmaf(q1,k2v,acc[1][2]); acc[1][3]=fmaf(q1,k3v,acc[1][3]);
        acc[2][0]=fmaf(q2,k0,acc[2][0]); acc[2][1]=fmaf(q2,k1v,acc[2][1]); acc[2][2]=fmaf(q2,k2v,acc[2][2]); acc[2][3]=fmaf(q2,k3v,acc[2][3]);
        acc[3][0]=fmaf(q3,k0,acc[3][0]); acc[3][1]=fmaf(q3,k1v,acc[3][1]); acc[3][2]=fmaf(q3,k2v,acc[3][2]); acc[3][3]=fmaf(q3,k3v,acc[3][3]);
    }
    #pragma unroll
    for (int i=0;i<4;i++)
        #pragma unroll
        for (int j=0;j<4;j++)
            red[sub*1024 + (h*16+d4*4+i)*16 + (e4*4+j)] = acc[i][j];
    if (t < 64){
        const float* qr=qs+t*TP;
        float a0=0,a1=0,a2=0,a3=0;
        for (int pp=0;pp<CHUNK;pp+=4){
            a0=fmaf(qr[pp+0],qr[pp+0],a0); a1=fmaf(qr[pp+1],qr[pp+1],a1);
            a2=fmaf(qr[pp+2],qr[pp+2],a2); a3=fmaf(qr[pp+3],qr[pp+3],a3);
        }
        g_sqp[(b*128+chunk)*64+t]=(a0+a1)+(a2+a3);
    } else if (t < 128){
        int ch=t-64;
        const float* kr=ks+ch*TP;
        float a0=0,a1=0,a2=0,a3=0;
        for (int pp=0;pp<CHUNK;pp+=4){
            a0=fmaf(kr[pp+0],kr[pp+0],a0); a1=fmaf(kr[pp+1],kr[pp+1],a1);
            a2=fmaf(kr[pp+2],kr[pp+2],a2); a3=fmaf(kr[pp+3],kr[pp+3],a3);
        }
        g_skp[(b*128+chunk)*64+ch]=(a0+a1)+(a2+a3);
    }
    __syncthreads();
    float* gout = g_Gpart + (b*128+chunk)*1024;
    for (int idx=t; idx<1024; idx+=256)
        gout[idx] = (red[idx]+red[1024+idx]) + (red[2048+idx]+red[3072+idx]);
}

// ------------ k4: reduce + softmax + fold A into wo --------------------------
__global__ void k4(const float* __restrict__ rescale, const float* __restrict__ wo)
{
    __shared__ float sG[1024];
    __shared__ float snq[64], snk[64];
    __shared__ float sA[1024];
    __shared__ float swo[4096];
    int b=blockIdx.x, t=threadIdx.x;
    {
        float a0=0.f,a1=0.f,a2=0.f,a3=0.f;
        for (int c=0;c<128;c++){
            const float4 v = ((const float4*)(g_Gpart+(b*128+c)*1024))[t];
            a0+=v.x; a1+=v.y; a2+=v.z; a3+=v.w;
        }
        sG[t*4+0]=a0; sG[t*4+1]=a1; sG[t*4+2]=a2; sG[t*4+3]=a3;
    }
    if (t<64){
        float aq=0.f, ak=0.f;
        for (int c=0;c<128;c++){ aq+=g_sqp[(b*128+c)*64+t]; ak+=g_skp[(b*128+c)*64+t]; }
        snq[t]=sqrtf(aq)+1e-8f; snk[t]=sqrtf(ak)+1e-8f;
    }
    for (int i=t;i<4096;i+=256) swo[i]=wo[i];
    __syncthreads();
    if (t<64){
        int h=t>>4;
        float r=rescale[h], nq=snq[t];
        float ev[16]; float mx=-1e30f;
        #pragma unroll
        for (int e=0;e<16;e++){ ev[e]=sG[t*16+e]/(nq*snk[h*16+e])*r; mx=fmaxf(mx,ev[e]); }
        float ss=0.f;
        #pragma unroll
        for (int e=0;e<16;e++){ ev[e]=expf(ev[e]-mx); ss+=ev[e]; }
        float inv=1.f/ss;
        #pragma unroll
        for (int e=0;e<16;e++) sA[t*16+e]=ev[e]*inv;
    }
    __syncthreads();
    for (int idx=t; idx<4096; idx+=256){
        int cp=idx>>6, e=idx&63, h=e>>4, e15=e&15;
        float acc=0.f;
        #pragma unroll
        for (int d=0;d<16;d++)
            acc = fmaf(sA[h*256 + d*16 + e15], swo[(h*16+d)*64 + cp], acc);
        g_weffT[b*4096 + cp*64 + e] = acc;
    }
}

// ------------ k5: out = v @ WeffT + bo + xm  (2 px/thread) --------------------
__global__ void __launch_bounds__(256,1)
k5(const float* __restrict__ bo, float* __restrict__ out)
{
    __shared__ __align__(16) float sw[4096];
    __shared__ float sbo[64];
    int t=threadIdx.x;
    int gp0=blockIdx.x*512+t, gp1=gp0+256;
    int b=gp0>>14, p0=gp0&(NPIX-1), p1=p0+256;
    for (int i=t;i<4096;i+=256) sw[i]=g_weffT[b*4096+i];
    if (t<64) sbo[t]=bo[t];
    u64 vp0[32], vp1[32];
    #pragma unroll
    for (int e2=0;e2<32;e2++){ vp0[e2]=g_vP[e2*BN+gp0]; vp1[e2]=g_vP[e2*BN+gp1]; }
    __syncthreads();
    #pragma unroll 2
    for (int cp=0;cp<64;cp+=2){
        float d00,d10; dot64p_dual(sw+cp*64,     vp0, vp1, d00, d10);
        float d01,d11; dot64p_dual(sw+(cp+1)*64, vp0, vp1, d01, d11);
        float xa0,xa1; unpack2(g_xmP[(cp>>1)*BN+gp0], xa0, xa1);
        float xb0,xb1; unpack2(g_xmP[(cp>>1)*BN+gp1], xb0, xb1);
        size_t r0=(size_t)(b*64+cp)*NPIX, r1=(size_t)(b*64+cp+1)*NPIX;
        out[r0+p0]=d00+sbo[cp]+xa0;
        out[r1+p0]=d01+sbo[cp+1]+xa1;
        out[r0+p1]=d10+sbo[cp]+xb0;
        out[r1+p1]=d11+sbo[cp+1]+xb1;
    }
}

// ------------ launch ----------------------------------------------------------
extern "C" void kernel_launch(void* const* d_in, const int* in_sizes, int n_in,
                              void* d_out, int out_size)
{
    const float* x   =(const float*)d_in[0];
    const float* sem =(const float*)d_in[1];
    const float* wa  =(const float*)d_in[2];
    const float* ba  =(const float*)d_in[3];
    const float* wb  =(const float*)d_in[4];
    const float* bb  =(const float*)d_in[5];
    const float* inw =(const float*)d_in[6];
    const float* inb =(const float*)d_in[7];
    const float* w1  =(const float*)d_in[8];
    const float* b1  =(const float*)d_in[9];
    const float* gm1 =(const float*)d_in[10];
    const float* be1 =(const float*)d_in[11];
    const float* w2  =(const float*)d_in[12];
    const float* b2  =(const float*)d_in[13];
    const float* gm2 =(const float*)d_in[14];
    const float* be2 =(const float*)d_in[15];
    const float* w3  =(const float*)d_in[16];
    const float* b3  =(const float*)d_in[17];
    const float* wq  =(const float*)d_in[18];
    const float* bq  =(const float*)d_in[19];
    const float* wk  =(const float*)d_in[20];
    const float* bk  =(const float*)d_in[21];
    const float* wv  =(const float*)d_in[22];
    const float* bv  =(const float*)d_in[23];
    const float* wo  =(const float*)d_in[24];
    const float* bo  =(const float*)d_in[25];
    const float* rescale=(const float*)d_in[26];
    float* out=(float*)d_out;

    cudaFuncSetAttribute(k1, cudaFuncAttributeMaxDynamicSharedMemorySize, 23232*4);
    cudaFuncSetAttribute(k2, cudaFuncAttributeMaxDynamicSharedMemorySize, 9088*4);
    cudaFuncSetAttribute(k3, cudaFuncAttributeMaxDynamicSharedMemorySize, (128*TP+4096)*4);

    kprep<<<64,256>>>(wa,ba,wb,bb,wq,w1,w2);
    kfold<<<32,256>>>(inw,inb,wk,bk,wv,bv);
    k1<<<128,256,23232*4>>>(x,sem);
    k2<<<128,256,9088*4>>>(x,b1,gm1,be1,b2,gm2,be2,w3,b3,bq);
    k3<<<dim3(128,4),256,(128*TP+4096)*4>>>();
    k4<<<4,256>>>(rescale,wo);
    k5<<<128,256>>>(bo,out);
}

// round 10
// speedup vs baseline: 1.2144x; 1.2144x over previous
#include <cuda_runtime.h>
#include <math.h>

#define NPIX 16384
#define BN   65536   // 4 * 16384

typedef unsigned long long u64;

// ------------ scratch ------------------------------------------------------
__device__ float g_k[64*BN];
__device__ float g_v[64*BN];
__device__ float g_q[64*BN];
__device__ float g_xm[64*BN];
__device__ float g_Gpart[4*128*1024];
__device__ float g_sqp[4*128*64];
__device__ float g_skp[4*128*64];
__device__ float g_weffT[4*4096];
__device__ float g_wcatT[4096];
__device__ float g_wikT[4096];
__device__ float g_wivT[4096];
__device__ float g_bcat[64];
__device__ float g_bik[64];
__device__ float g_biv[64];

// ------------ f32x2 helpers --------------------------------------------------
__device__ __forceinline__ u64 pack2(float lo, float hi){
    u64 r; asm("mov.b64 %0, {%1,%2};" : "=l"(r) : "f"(lo), "f"(hi)); return r;
}
__device__ __forceinline__ void unpack2(u64 a, float& lo, float& hi){
    asm("mov.b64 {%0,%1}, %2;" : "=f"(lo), "=f"(hi) : "l"(a));
}
__device__ __forceinline__ u64 fma2_(u64 a, u64 b, u64 c){
    u64 d; asm("fma.rn.f32x2 %0, %1, %2, %3;" : "=l"(d) : "l"(a), "l"(b), "l"(c)); return d;
}
__device__ __forceinline__ u64 add2_(u64 a, u64 b){
    u64 d; asm("add.rn.f32x2 %0, %1, %2;" : "=l"(d) : "l"(a), "l"(b)); return d;
}
__device__ __forceinline__ float hadd2(u64 a){
    float lo, hi; unpack2(a, lo, hi); return lo + hi;
}

// single-pixel 64-dot (for k1/k5)
__device__ __forceinline__ float dot64p(const float* w, const u64* xp){
    const ulonglong2* w2 = (const ulonglong2*)w;
    u64 a0=0ull,a1=0ull,a2=0ull,a3=0ull;
    #pragma unroll
    for (int i=0;i<8;i++){
        ulonglong2 wa=w2[2*i], wb=w2[2*i+1];
        a0=fma2_(xp[4*i+0], wa.x, a0);
        a1=fma2_(xp[4*i+1], wa.y, a1);
        a2=fma2_(xp[4*i+2], wb.x, a2);
        a3=fma2_(xp[4*i+3], wb.y, a3);
    }
    return hadd2(add2_(add2_(a0,a1),add2_(a2,a3)));
}

// ------------ kprep: fold + transpose class weights -------------------------
__global__ void kprep(const float* wa, const float* ba, const float* wb, const float* bb)
{
    int t = blockIdx.x*256 + threadIdx.x;     // 0..4095
    if (t < 4096) {
        int j = t>>6, c = t&63;
        float w;
        if (j < 4) w = wa[c*4 + j];
        else { int u=j-4; int kk=u/3; int d=u-kk*3; w = wb[kk*192 + c*3 + d]; }
        g_wcatT[t] = w;
    }
    if (t < 64) g_bcat[t] = (t < 4) ? ba[t] : bb[t-4];
}

__global__ void kfold(const float* inw, const float* inb,
                      const float* wk, const float* bk,
                      const float* wv, const float* bv)
{
    int t = blockIdx.x*256 + threadIdx.x;     // 0..8191
    int o = (t>>6)&63, c = t&63;
    const float* wx = (t < 4096) ? wk : wv;
    float acc = 0.f;
    #pragma unroll 4
    for (int m=0;m<64;m++) acc = fmaf(inw[c*64+m], wx[m*64+o], acc);
    if (t < 4096) g_wikT[o*64+c] = acc;
    else          g_wivT[o*64+c] = acc;
    if (t < 64) {
        float a=0.f, b2=0.f;
        for (int m=0;m<64;m++){ a=fmaf(inb[m],wk[m*64+t],a); b2=fmaf(inb[m],wv[m*64+t],b2); }
        g_bik[t] = a + bk[t];
        g_biv[t] = b2 + bv[t];
    }
}

// ------------ k1: feat path -> k, v (R8 champion version) --------------------
__global__ void __launch_bounds__(256,1)
k1(const float* __restrict__ x, const float* __restrict__ sem)
{
    extern __shared__ float smx[];
    float* s_w    = smx;            // wcatT | wikT | wivT
    float* s_sem  = smx + 12288;
    float* s_bias = smx + 17664;
    int t = threadIdx.x;
    int gp = blockIdx.x*256 + t;
    int b = gp >> 14, p = gp & (NPIX-1);

    for (int i=t;i<4096;i+=256){
        s_w[i]      = g_wcatT[i];
        s_w[4096+i] = g_wikT[i];
        s_w[8192+i] = g_wivT[i];
    }
    if (t<64){ s_bias[t]=g_bcat[t]; s_bias[64+t]=g_bik[t]; s_bias[128+t]=g_biv[t]; }
    int sbase = b*21*NPIX + p;
    #pragma unroll
    for (int kk=0;kk<21;kk++){ float sv=sem[sbase+kk*NPIX]; s_sem[kk*256+t]=sv>0.f?sv:0.f; }

    u64 xp[32];
    int xbase = b*64*NPIX + p;
    #pragma unroll
    for (int c=0;c<64;c+=2) xp[c>>1]=pack2(x[xbase+c*NPIX], x[xbase+(c+1)*NPIX]);
    __syncthreads();

    u64 ap[32];
    #pragma unroll 2
    for (int j=0;j<64;j+=2){
        float d0 = dot64p(s_w + j*64, xp);
        float d1 = dot64p(s_w + (j+1)*64, xp);
        int cls0 = (j   < 4) ? 0 : ((j-4)/3 + 1);
        int cls1 = (j+1 < 4) ? 0 : ((j-3)/3 + 1);
        ap[j>>1] = pack2(s_sem[cls0*256+t]*d0 + s_bias[j],
                         s_sem[cls1*256+t]*d1 + s_bias[j+1]);
    }
    #pragma unroll 2
    for (int o=0;o<64;o++) g_k[o*BN+gp] = dot64p(s_w + 4096 + o*64, ap) + s_bias[64+o];
    #pragma unroll 2
    for (int o=0;o<64;o++) g_v[o*BN+gp] = dot64p(s_w + 8192 + o*64, ap) + s_bias[128+o];
}

// ------------ k2: GEMM-tiled LN-MLP -> xm, q ----------------------------------
// CTA = 64 pixels (32 f32x2 pixel-pairs). smem: Wf 8192f | R1 4096u64 | R2 4096u64
// | s_p 896f | stats. Total 26624 f = 106496 B. 2 CTA/SM.
__device__ __forceinline__ void ln_lrelu(u64* R, const float* g, const float* be,
                                         u64* SS, u64* SS2, u64* mP, u64* rP, int t)
{
    __syncthreads();
    const float inv_n = 1.f/128.f;
    int pr = t & 31, seg = t >> 5;
    u64 s=0ull, s2=0ull;
    #pragma unroll 4
    for (int o=seg*16; o<seg*16+16; o++){ u64 v=R[o*32+pr]; s=add2_(s,v); s2=fma2_(v,v,s2); }
    SS[seg*32+pr]=s; SS2[seg*32+pr]=s2;
    __syncthreads();
    if (t < 32){
        u64 a=0ull, a2=0ull;
        #pragma unroll
        for (int sg=0;sg<8;sg++){ a=add2_(a,SS[sg*32+t]); a2=add2_(a2,SS2[sg*32+t]); }
        float slo,shi,qlo,qhi; unpack2(a,slo,shi); unpack2(a2,qlo,qhi);
        float m0=slo*inv_n, m1=shi*inv_n;
        float r0=rsqrtf(qlo*inv_n - m0*m0 + 1e-5f);
        float r1=rsqrtf(qhi*inv_n - m1*m1 + 1e-5f);
        mP[t]=pack2(m0,m1); rP[t]=pack2(r0,r1);
    }
    __syncthreads();
    #pragma unroll 4
    for (int idx=t; idx<4096; idx+=256){
        int o=idx>>5, p=idx&31;
        float vlo,vhi,mlo,mhi,rlo,rhi;
        unpack2(R[idx],vlo,vhi); unpack2(mP[p],mlo,mhi); unpack2(rP[p],rlo,rhi);
        float gg=g[o], bb=be[o];
        float h0=(vlo-mlo)*rlo*gg+bb;
        float h1=(vhi-mhi)*rhi*gg+bb;
        h0 = h0>0.f?h0:0.01f*h0;
        h1 = h1>0.f?h1:0.01f*h1;
        R[idx]=pack2(h0,h1);
    }
    __syncthreads();
}

#define GEMM_STEP_16(WPTR, XPTR, KIDX, OIDX, PIDX, ACC) do { \
    const float4 wv = *(const float4*)((WPTR) + (KIDX)*128 + (OIDX)); \
    const ulonglong2 xa = *(const ulonglong2*)((XPTR) + (KIDX)*32 + (PIDX)); \
    const ulonglong2 xb = *(const ulonglong2*)((XPTR) + (KIDX)*32 + (PIDX) + 2); \
    u64 wd0=pack2(wv.x,wv.x), wd1=pack2(wv.y,wv.y), wd2=pack2(wv.z,wv.z), wd3=pack2(wv.w,wv.w); \
    ACC[0][0]=fma2_(xa.x,wd0,ACC[0][0]); ACC[0][1]=fma2_(xa.y,wd0,ACC[0][1]); \
    ACC[0][2]=fma2_(xb.x,wd0,ACC[0][2]); ACC[0][3]=fma2_(xb.y,wd0,ACC[0][3]); \
    ACC[1][0]=fma2_(xa.x,wd1,ACC[1][0]); ACC[1][1]=fma2_(xa.y,wd1,ACC[1][1]); \
    ACC[1][2]=fma2_(xb.x,wd1,ACC[1][2]); ACC[1][3]=fma2_(xb.y,wd1,ACC[1][3]); \
    ACC[2][0]=fma2_(xa.x,wd2,ACC[2][0]); ACC[2][1]=fma2_(xa.y,wd2,ACC[2][1]); \
    ACC[2][2]=fma2_(xb.x,wd2,ACC[2][2]); ACC[2][3]=fma2_(xb.y,wd2,ACC[2][3]); \
    ACC[3][0]=fma2_(xa.x,wd3,ACC[3][0]); ACC[3][1]=fma2_(xa.y,wd3,ACC[3][1]); \
    ACC[3][2]=fma2_(xb.x,wd3,ACC[3][2]); ACC[3][3]=fma2_(xb.y,wd3,ACC[3][3]); \
} while(0)

__global__ void __launch_bounds__(256,2)
k2(const float* __restrict__ x,
   const float* __restrict__ w1, const float* __restrict__ b1,
   const float* __restrict__ gm1, const float* __restrict__ be1,
   const float* __restrict__ w2, const float* __restrict__ b2,
   const float* __restrict__ gm2, const float* __restrict__ be2,
   const float* __restrict__ w3, const float* __restrict__ b3,
   const float* __restrict__ wq, const float* __restrict__ bq)
{
    extern __shared__ float smx[];
    float* Wf  = smx;                       // 8192 f
    u64*   R1  = (u64*)(smx + 8192);        // 4096 u64
    u64*   R2  = (u64*)(smx + 16384);       // 4096 u64
    float* s_p = smx + 24576;               // 896 f
    u64*   SS  = (u64*)(smx + 25472);       // 256 u64
    u64*   SS2 = (u64*)(smx + 25984);       // 256 u64
    u64*   mP  = (u64*)(smx + 26496);       // 32 u64
    u64*   rP  = (u64*)(smx + 26560);       // 32 u64

    int t = threadIdx.x;
    int gp0 = blockIdx.x*64;
    int b = gp0 >> 14, pb = gp0 & (NPIX-1);
    int xbase = b*64*NPIX + pb;

    if (t < 128){
        s_p[t]=b1[t]; s_p[128+t]=gm1[t]; s_p[256+t]=be1[t];
        s_p[384+t]=b2[t]; s_p[512+t]=gm2[t]; s_p[640+t]=be2[t];
    }
    if (t < 64){ s_p[768+t]=b3[t]; s_p[832+t]=bq[t]; }

    for (int i=t;i<8192;i+=256) Wf[i]=w1[i];
    for (int i=t;i<2048;i+=256){
        int c=i>>5, pr=i&31;
        R1[i] = pack2(x[xbase + c*NPIX + pr], x[xbase + c*NPIX + 32 + pr]);
    }
    __syncthreads();

    // ---- GEMM1: u1[128o][32pr] = x @ w1 + b1 -> R2 ----
    int tp = t & 7,  to = t >> 3;      // to 0..31
    int o4 = to*4,   pr4 = tp*4;
    u64 acc[4][4];
    #pragma unroll
    for (int j=0;j<4;j++){ acc[j][0]=0ull; acc[j][1]=0ull; acc[j][2]=0ull; acc[j][3]=0ull; }
    #pragma unroll 4
    for (int k=0;k<64;k++) GEMM_STEP_16(Wf, R1, k, o4, pr4, acc);
    #pragma unroll
    for (int j=0;j<4;j++){
        u64 bb = pack2(s_p[o4+j], s_p[o4+j]);
        #pragma unroll
        for (int pp=0;pp<4;pp++) R2[(o4+j)*32 + pr4+pp] = add2_(acc[j][pp], bb);
    }

    ln_lrelu(R2, s_p+128, s_p+256, SS, SS2, mP, rP, t);

    // ---- GEMM2: u2 = h1 @ w2 + b2 -> R1 (two staged halves) ----
    for (int i=t;i<8192;i+=256) Wf[i]=w2[i];
    __syncthreads();
    #pragma unroll
    for (int j=0;j<4;j++){ acc[j][0]=0ull; acc[j][1]=0ull; acc[j][2]=0ull; acc[j][3]=0ull; }
    #pragma unroll 4
    for (int k=0;k<64;k++) GEMM_STEP_16(Wf, R2, k, o4, pr4, acc);
    __syncthreads();
    for (int i=t;i<8192;i+=256) Wf[i]=w2[8192+i];
    __syncthreads();
    #pragma unroll 4
    for (int k=0;k<64;k++) GEMM_STEP_16(Wf, R2+64*32, k, o4, pr4, acc);
    #pragma unroll
    for (int j=0;j<4;j++){
        u64 bb = pack2(s_p[384+o4+j], s_p[384+o4+j]);
        #pragma unroll
        for (int pp=0;pp<4;pp++) R1[(o4+j)*32 + pr4+pp] = add2_(acc[j][pp], bb);
    }

    ln_lrelu(R1, s_p+512, s_p+640, SS, SS2, mP, rP, t);

    // ---- GEMM3: xm[64o][32pr] = h2 @ w3 + b3 -> g_xm + R2 ----
    for (int i=t;i<8192;i+=256) Wf[i]=w3[i];
    __syncthreads();
    int tq = t & 15, tu = t >> 4;      // tu 0..15 -> o = tu*4 ; tq -> pr = tq*2
    int o4b = tu*4, pr2 = tq*2;
    u64 ac3[4][2];
    #pragma unroll
    for (int j=0;j<4;j++){ ac3[j][0]=0ull; ac3[j][1]=0ull; }
    #pragma unroll 4
    for (int k=0;k<128;k++){
        const float4 wv = *(const float4*)(Wf + k*64 + o4b);
        const ulonglong2 xa = *(const ulonglong2*)(R1 + k*32 + pr2);
        u64 wd0=pack2(wv.x,wv.x), wd1=pack2(wv.y,wv.y), wd2=pack2(wv.z,wv.z), wd3=pack2(wv.w,wv.w);
        ac3[0][0]=fma2_(xa.x,wd0,ac3[0][0]); ac3[0][1]=fma2_(xa.y,wd0,ac3[0][1]);
        ac3[1][0]=fma2_(xa.x,wd1,ac3[1][0]); ac3[1][1]=fma2_(xa.y,wd1,ac3[1][1]);
        ac3[2][0]=fma2_(xa.x,wd2,ac3[2][0]); ac3[2][1]=fma2_(xa.y,wd2,ac3[2][1]);
        ac3[3][0]=fma2_(xa.x,wd3,ac3[3][0]); ac3[3][1]=fma2_(xa.y,wd3,ac3[3][1]);
    }
    #pragma unroll
    for (int j=0;j<4;j++){
        int o = o4b + j;
        u64 bb = pack2(s_p[768+o], s_p[768+o]);
        #pragma unroll
        for (int pp=0;pp<2;pp++){
            u64 v = add2_(ac3[j][pp], bb);
            R2[o*32 + pr2+pp] = v;
            float lo,hi; unpack2(v,lo,hi);
            g_xm[o*BN + gp0 + pr2+pp]      = lo;
            g_xm[o*BN + gp0 + 32 + pr2+pp] = hi;
        }
    }
    __syncthreads();

    // ---- q-GEMM: q = xm @ wq + bq ----
    for (int i=t;i<4096;i+=256) Wf[i]=wq[i];
    __syncthreads();
    u64 acq[4][2];
    #pragma unroll
    for (int j=0;j<4;j++){ acq[j][0]=0ull; acq[j][1]=0ull; }
    #pragma unroll 4
    for (int k=0;k<64;k++){
        const float4 wv = *(const float4*)(Wf + k*64 + o4b);
        const ulonglong2 xa = *(const ulonglong2*)(R2 + k*32 + pr2);
        u64 wd0=pack2(wv.x,wv.x), wd1=pack2(wv.y,wv.y), wd2=pack2(wv.z,wv.z), wd3=pack2(wv.w,wv.w);
        acq[0][0]=fma2_(xa.x,wd0,acq[0][0]); acq[0][1]=fma2_(xa.y,wd0,acq[0][1]);
        acq[1][0]=fma2_(xa.x,wd1,acq[1][0]); acq[1][1]=fma2_(xa.y,wd1,acq[1][1]);
        acq[2][0]=fma2_(xa.x,wd2,acq[2][0]); acq[2][1]=fma2_(xa.y,wd2,acq[2][1]);
        acq[3][0]=fma2_(xa.x,wd3,acq[3][0]); acq[3][1]=fma2_(xa.y,wd3,acq[3][1]);
    }
    #pragma unroll
    for (int j=0;j<4;j++){
        int o = o4b + j;
        u64 bb = pack2(s_p[832+o], s_p[832+o]);
        #pragma unroll
        for (int pp=0;pp<2;pp++){
            u64 v = add2_(acq[j][pp], bb);
            float lo,hi; unpack2(v,lo,hi);
            g_q[o*BN + gp0 + pr2+pp]      = lo;
            g_q[o*BN + gp0 + 32 + pr2+pp] = hi;
        }
    }
}

// ------------ k3: Gram + norm partials per 128-pixel chunk -------------------
#define CHUNK 128
#define TP 129
__global__ void __launch_bounds__(256,2) k3()
{
    extern __shared__ float smx[];
    float* qs  = smx;
    float* ks  = smx + 64*TP;
    float* red = smx + 128*TP;
    int t = threadIdx.x;
    int chunk = blockIdx.x, b = blockIdx.y;
    int pbase = b*NPIX + chunk*CHUNK;
    for (int i=t; i<64*CHUNK; i+=256){
        int ch=i>>7, pp=i&(CHUNK-1);
        qs[ch*TP+pp]=g_q[ch*BN+pbase+pp];
        ks[ch*TP+pp]=g_k[ch*BN+pbase+pp];
    }
    __syncthreads();
    int sub=t>>6, combo=t&63;
    int h=combo>>4, d4=(combo>>2)&3, e4=combo&3;
    const float* qsb=qs+(h*16+d4*4)*TP;
    const float* ksb=ks+(h*16+e4*4)*TP;
    float acc[4][4];
    #pragma unroll
    for (int i=0;i<4;i++)
        #pragma unroll
        for (int j=0;j<4;j++) acc[i][j]=0.f;
    for (int pp=sub*32; pp<sub*32+32; pp++){
        float q0=qsb[pp],q1=qsb[TP+pp],q2=qsb[2*TP+pp],q3=qsb[3*TP+pp];
        float k0=ksb[pp],k1v=ksb[TP+pp],k2v=ksb[2*TP+pp],k3v=ksb[3*TP+pp];
        acc[0][0]=fmaf(q0,k0,acc[0][0]); acc[0][1]=fmaf(q0,k1v,acc[0][1]); acc[0][2]=fmaf(q0,k2v,acc[0][2]); acc[0][3]=fmaf(q0,k3v,acc[0][3]);
        acc[1][0]=fmaf(q1,k0,acc[1][0]); acc[1][1]=fmaf(q1,k1v,acc[1][1]); acc[1][2]=fmaf(q1,k2v,acc[1][2]); acc[1][3]=fmaf(q1,k3v,acc[1][3]);
        acc[2][0]=fmaf(q2,k0,acc[2][0]); acc[2][1]=fmaf(q2,k1v,acc[2][1]); acc[2][2]=fmaf(q2,k2v,acc[2][2]); acc[2][3]=fmaf(q2,k3v,acc[2][3]);
        acc[3][0]=fmaf(q3,k0,acc[3][0]); acc[3][1]=fmaf(q3,k1v,acc[3][1]); acc[3][2]=fmaf(q3,k2v,acc[3][2]); acc[3][3]=fmaf(q3,k3v,acc[3][3]);
    }
    #pragma unroll
    for (int i=0;i<4;i++)
        #pragma unroll
        for (int j=0;j<4;j++)
            red[sub*1024 + (h*16+d4*4+i)*16 + (e4*4+j)] = acc[i][j];
    if (t < 64){
        const float* qr=qs+t*TP;
        float a0=0,a1=0,a2=0,a3=0;
        for (int pp=0;pp<CHUNK;pp+=4){
            a0=fmaf(qr[pp+0],qr[pp+0],a0); a1=fmaf(qr[pp+1],qr[pp+1],a1);
            a2=fmaf(qr[pp+2],qr[pp+2],a2); a3=fmaf(qr[pp+3],qr[pp+3],a3);
        }
        g_sqp[(b*128+chunk)*64+t]=(a0+a1)+(a2+a3);
    } else if (t < 128){
        int ch=t-64;
        const float* kr=ks+ch*TP;
        float a0=0,a1=0,a2=0,a3=0;
        for (int pp=0;pp<CHUNK;pp+=4){
            a0=fmaf(kr[pp+0],kr[pp+0],a0); a1=fmaf(kr[pp+1],kr[pp+1],a1);
            a2=fmaf(kr[pp+2],kr[pp+2],a2); a3=fmaf(kr[pp+3],kr[pp+3],a3);
        }
        g_skp[(b*128+chunk)*64+ch]=(a0+a1)+(a2+a3);
    }
    __syncthreads();
    float* gout = g_Gpart + (b*128+chunk)*1024;
    for (int idx=t; idx<1024; idx+=256)
        gout[idx] = (red[idx]+red[1024+idx]) + (red[2048+idx]+red[3072+idx]);
}

// ------------ k4: reduce + softmax + fold A into wo --------------------------
__global__ void k4(const float* __restrict__ rescale, const float* __restrict__ wo)
{
    __shared__ float sG[1024];
    __shared__ float snq[64], snk[64];
    __shared__ float sA[1024];
    __shared__ float swo[4096];
    int b=blockIdx.x, t=threadIdx.x;
    {
        float a0=0.f,a1=0.f,a2=0.f,a3=0.f;
        for (int c=0;c<128;c++){
            const float4 v = ((const float4*)(g_Gpart+(b*128+c)*1024))[t];
            a0+=v.x; a1+=v.y; a2+=v.z; a3+=v.w;
        }
        sG[t*4+0]=a0; sG[t*4+1]=a1; sG[t*4+2]=a2; sG[t*4+3]=a3;
    }
    if (t<64){
        float aq=0.f, ak=0.f;
        for (int c=0;c<128;c++){ aq+=g_sqp[(b*128+c)*64+t]; ak+=g_skp[(b*128+c)*64+t]; }
        snq[t]=sqrtf(aq)+1e-8f; snk[t]=sqrtf(ak)+1e-8f;
    }
    for (int i=t;i<4096;i+=256) swo[i]=wo[i];
    __syncthreads();
    if (t<64){
        int h=t>>4;
        float r=rescale[h], nq=snq[t];
        float ev[16]; float mx=-1e30f;
        #pragma unroll
        for (int e=0;e<16;e++){ ev[e]=sG[t*16+e]/(nq*snk[h*16+e])*r; mx=fmaxf(mx,ev[e]); }
        float ss=0.f;
        #pragma unroll
        for (int e=0;e<16;e++){ ev[e]=expf(ev[e]-mx); ss+=ev[e]; }
        float inv=1.f/ss;
        #pragma unroll
        for (int e=0;e<16;e++) sA[t*16+e]=ev[e]*inv;
    }
    __syncthreads();
    for (int idx=t; idx<4096; idx+=256){
        int cp=idx>>6, e=idx&63, h=e>>4, e15=e&15;
        float acc=0.f;
        #pragma unroll
        for (int d=0;d<16;d++)
            acc = fmaf(sA[h*256 + d*16 + e15], swo[(h*16+d)*64 + cp], acc);
        g_weffT[b*4096 + cp*64 + e] = acc;
    }
}

// ------------ k5: out = v @ WeffT + bo + xm ----------------------------------
__global__ void __launch_bounds__(256,2)
k5(const float* __restrict__ bo, float* __restrict__ out)
{
    __shared__ __align__(16) float sw[4096];
    __shared__ float sbo[64];
    int t=threadIdx.x;
    int gp=blockIdx.x*256+t;
    int b=gp>>14, p=gp&(NPIX-1);
    for (int i=t;i<4096;i+=256) sw[i]=g_weffT[b*4096+i];
    if (t<64) sbo[t]=bo[t];
    u64 vp[32];
    #pragma unroll
    for (int e=0;e<64;e+=2) vp[e>>1]=pack2(g_v[e*BN+gp], g_v[(e+1)*BN+gp]);
    __syncthreads();
    #pragma unroll 2
    for (int cp=0;cp<64;cp++){
        float d = dot64p(sw+cp*64, vp) + sbo[cp] + g_xm[cp*BN+gp];
        out[(size_t)(b*64+cp)*NPIX + p] = d;
    }
}

// ------------ launch ----------------------------------------------------------
extern "C" void kernel_launch(void* const* d_in, const int* in_sizes, int n_in,
                              void* d_out, int out_size)
{
    const float* x   =(const float*)d_in[0];
    const float* sem =(const float*)d_in[1];
    const float* wa  =(const float*)d_in[2];
    const float* ba  =(const float*)d_in[3];
    const float* wb  =(const float*)d_in[4];
    const float* bb  =(const float*)d_in[5];
    const float* inw =(const float*)d_in[6];
    const float* inb =(const float*)d_in[7];
    const float* w1  =(const float*)d_in[8];
    const float* b1  =(const float*)d_in[9];
    const float* gm1 =(const float*)d_in[10];
    const float* be1 =(const float*)d_in[11];
    const float* w2  =(const float*)d_in[12];
    const float* b2  =(const float*)d_in[13];
    const float* gm2 =(const float*)d_in[14];
    const float* be2 =(const float*)d_in[15];
    const float* w3  =(const float*)d_in[16];
    const float* b3  =(const float*)d_in[17];
    const float* wq  =(const float*)d_in[18];
    const float* bq  =(const float*)d_in[19];
    const float* wk  =(const float*)d_in[20];
    const float* bk  =(const float*)d_in[21];
    const float* wv  =(const float*)d_in[22];
    const float* bv  =(const float*)d_in[23];
    const float* wo  =(const float*)d_in[24];
    const float* bo  =(const float*)d_in[25];
    const float* rescale=(const float*)d_in[26];
    float* out=(float*)d_out;

    cudaFuncSetAttribute(k1, cudaFuncAttributeMaxDynamicSharedMemorySize, 17856*4);
    cudaFuncSetAttribute(k2, cudaFuncAttributeMaxDynamicSharedMemorySize, 26624*4);
    cudaFuncSetAttribute(k3, cudaFuncAttributeMaxDynamicSharedMemorySize, (128*TP+4096)*4);

    kprep<<<16,256>>>(wa,ba,wb,bb);
    kfold<<<32,256>>>(inw,inb,wk,bk,wv,bv);
    k1<<<256,256,17856*4>>>(x,sem);
    k2<<<1024,256,26624*4>>>(x,w1,b1,gm1,be1,w2,b2,gm2,be2,w3,b3,wq,bq);
    k3<<<dim3(128,4),256,(128*TP+4096)*4>>>();
    k4<<<4,256>>>(rescale,wo);
    k5<<<256,256>>>(bo,out);
}

// round 11
// speedup vs baseline: 1.3255x; 1.0915x over previous
#include <cuda_runtime.h>
#include <math.h>

#define NPIX 16384
#define BN   65536   // 4 * 16384

typedef unsigned long long u64;

// ------------ scratch ------------------------------------------------------
__device__ float g_k[64*BN];
__device__ float g_v[64*BN];
__device__ float g_q[64*BN];
__device__ float g_xm[64*BN];
__device__ float g_Gpart[4*128*1024];
__device__ float g_sqp[4*128*64];
__device__ float g_skp[4*128*64];
__device__ float g_weff[4*4096];     // [b][e*64+cp]
__device__ float g_wcat[4096];       // [c][j]
__device__ float g_wik[4096];        // (in_w@wk) [c][o]
__device__ float g_wiv[4096];        // (in_w@wv) [c][o]
__device__ float g_bcat[64];
__device__ float g_bik[64];
__device__ float g_biv[64];

// ------------ f32x2 helpers --------------------------------------------------
__device__ __forceinline__ u64 pack2(float lo, float hi){
    u64 r; asm("mov.b64 %0, {%1,%2};" : "=l"(r) : "f"(lo), "f"(hi)); return r;
}
__device__ __forceinline__ void unpack2(u64 a, float& lo, float& hi){
    asm("mov.b64 {%0,%1}, %2;" : "=f"(lo), "=f"(hi) : "l"(a));
}
__device__ __forceinline__ u64 fma2_(u64 a, u64 b, u64 c){
    u64 d; asm("fma.rn.f32x2 %0, %1, %2, %3;" : "=l"(d) : "l"(a), "l"(b), "l"(c)); return d;
}
__device__ __forceinline__ u64 add2_(u64 a, u64 b){
    u64 d; asm("add.rn.f32x2 %0, %1, %2;" : "=l"(d) : "l"(a), "l"(b)); return d;
}

// swizzled tile index: R[o*32 + SWP(o,pair)]
__device__ __forceinline__ int SWP(int o, int p){
    return (p & 3) | ((((p >> 2) ^ (o >> 2)) & 7) << 2);
}

// ---- GEMM steps: warp 'wrp' owns pairs [4w,4w+4), lane owns outputs ----------
#define GSTEP128(W, R, RROW, KK) do{ \
    const float4 _wv = *(const float4*)((W)+(KK)*128+4*lane); \
    int _g = (((wrp)^((RROW)>>2))&7)<<2; \
    const ulonglong2 _xa = *(const ulonglong2*)((R)+(RROW)*32+_g); \
    const ulonglong2 _xb = *(const ulonglong2*)((R)+(RROW)*32+_g+2); \
    u64 _w0=pack2(_wv.x,_wv.x), _w1=pack2(_wv.y,_wv.y), _w2=pack2(_wv.z,_wv.z), _w3=pack2(_wv.w,_wv.w); \
    acc[0][0]=fma2_(_xa.x,_w0,acc[0][0]); acc[0][1]=fma2_(_xa.y,_w0,acc[0][1]); acc[0][2]=fma2_(_xb.x,_w0,acc[0][2]); acc[0][3]=fma2_(_xb.y,_w0,acc[0][3]); \
    acc[1][0]=fma2_(_xa.x,_w1,acc[1][0]); acc[1][1]=fma2_(_xa.y,_w1,acc[1][1]); acc[1][2]=fma2_(_xb.x,_w1,acc[1][2]); acc[1][3]=fma2_(_xb.y,_w1,acc[1][3]); \
    acc[2][0]=fma2_(_xa.x,_w2,acc[2][0]); acc[2][1]=fma2_(_xa.y,_w2,acc[2][1]); acc[2][2]=fma2_(_xb.x,_w2,acc[2][2]); acc[2][3]=fma2_(_xb.y,_w2,acc[2][3]); \
    acc[3][0]=fma2_(_xa.x,_w3,acc[3][0]); acc[3][1]=fma2_(_xa.y,_w3,acc[3][1]); acc[3][2]=fma2_(_xb.x,_w3,acc[3][2]); acc[3][3]=fma2_(_xb.y,_w3,acc[3][3]); \
}while(0)

#define GSTEP64(W, R, RROW, KK) do{ \
    const float2 _wv = *(const float2*)((W)+(KK)*64+2*lane); \
    int _g = (((wrp)^((RROW)>>2))&7)<<2; \
    const ulonglong2 _xa = *(const ulonglong2*)((R)+(RROW)*32+_g); \
    const ulonglong2 _xb = *(const ulonglong2*)((R)+(RROW)*32+_g+2); \
    u64 _w0=pack2(_wv.x,_wv.x), _w1=pack2(_wv.y,_wv.y); \
    acc2[0][0]=fma2_(_xa.x,_w0,acc2[0][0]); acc2[0][1]=fma2_(_xa.y,_w0,acc2[0][1]); acc2[0][2]=fma2_(_xb.x,_w0,acc2[0][2]); acc2[0][3]=fma2_(_xb.y,_w0,acc2[0][3]); \
    acc2[1][0]=fma2_(_xa.x,_w1,acc2[1][0]); acc2[1][1]=fma2_(_xa.y,_w1,acc2[1][1]); acc2[1][2]=fma2_(_xb.x,_w1,acc2[1][2]); acc2[1][3]=fma2_(_xb.y,_w1,acc2[1][3]); \
}while(0)

// ------------ LN + leaky-relu over swizzled 128x32 tile -----------------------
__device__ __forceinline__ void ln_swz(u64* R, const float* g, const float* be,
                                       u64* SS, u64* SS2, u64* mP, u64* rP, int t)
{
    __syncthreads();
    int pr = t & 31, seg = t >> 5;
    u64 s=0ull, s2=0ull;
    #pragma unroll 4
    for (int o=seg*16; o<seg*16+16; o++){
        u64 v = R[o*32 + SWP(o,pr)];
        s = add2_(s, v); s2 = fma2_(v, v, s2);
    }
    SS[seg*32+pr]=s; SS2[seg*32+pr]=s2;
    __syncthreads();
    if (t < 32){
        u64 a=0ull, a2=0ull;
        #pragma unroll
        for (int sg=0; sg<8; sg++){ a=add2_(a,SS[sg*32+t]); a2=add2_(a2,SS2[sg*32+t]); }
        float slo,shi,qlo,qhi; unpack2(a,slo,shi); unpack2(a2,qlo,qhi);
        float m0=slo*(1.f/128.f), m1=shi*(1.f/128.f);
        mP[t]=pack2(m0,m1);
        rP[t]=pack2(rsqrtf(qlo*(1.f/128.f)-m0*m0+1e-5f),
                    rsqrtf(qhi*(1.f/128.f)-m1*m1+1e-5f));
    }
    __syncthreads();
    #pragma unroll 4
    for (int idx=t; idx<4096; idx+=256){
        int o=idx>>5, p=idx&31;
        int ri = o*32 + SWP(o,p);
        float vlo,vhi,mlo,mhi,rlo,rhi;
        unpack2(R[ri],vlo,vhi); unpack2(mP[p],mlo,mhi); unpack2(rP[p],rlo,rhi);
        float gg=g[o], bb=be[o];
        float h0=(vlo-mlo)*rlo*gg+bb, h1=(vhi-mhi)*rhi*gg+bb;
        h0=h0>0.f?h0:0.01f*h0; h1=h1>0.f?h1:0.01f*h1;
        R[ri]=pack2(h0,h1);
    }
    __syncthreads();
}

// ------------ kprep: fold class weights [c][j] -------------------------------
__global__ void kprep(const float* wa, const float* ba, const float* wb, const float* bb)
{
    int t = blockIdx.x*256 + threadIdx.x;     // 0..4095
    if (t < 4096){
        int c = t>>6, j = t&63;
        float w;
        if (j < 4) w = wa[c*4 + j];
        else { int u=j-4; int kk=u/3; int d=u-kk*3; w = wb[kk*192 + c*3 + d]; }
        g_wcat[t] = w;
    }
    if (t < 64) g_bcat[t] = (t < 4) ? ba[t] : bb[t-4];
}

__global__ void kfold(const float* inw, const float* inb,
                      const float* wk, const float* bk,
                      const float* wv, const float* bv)
{
    int t = blockIdx.x*256 + threadIdx.x;     // 0..8191
    int c = (t>>6)&63, o = t&63;
    const float* wx = (t < 4096) ? wk : wv;
    float acc = 0.f;
    #pragma unroll 4
    for (int m=0;m<64;m++) acc = fmaf(inw[c*64+m], wx[m*64+o], acc);
    if (t < 4096) g_wik[c*64+o] = acc;
    else          g_wiv[c*64+o] = acc;
    if (t < 64){
        float a=0.f, b2=0.f;
        for (int m=0;m<64;m++){ a=fmaf(inb[m],wk[m*64+t],a); b2=fmaf(inb[m],wv[m*64+t],b2); }
        g_bik[t] = a + bk[t];
        g_biv[t] = b2 + bv[t];
    }
}

// ------------ k1: feat path -> k, v (GEMM tiles, 64 px/CTA) ------------------
// smem floats: wcat 4096 | wik 4096 | wiv 4096 | R1 4096 | R2 4096 | Ssem 1386 | bias 192
__global__ void __launch_bounds__(256,2)
k1(const float* __restrict__ x, const float* __restrict__ sem)
{
    extern __shared__ float smx[];
    float* s_wcat = smx;
    float* s_wik  = smx + 4096;
    float* s_wiv  = smx + 8192;
    u64*   R1     = (u64*)(smx + 12288);   // 2048 u64
    u64*   R2     = (u64*)(smx + 16384);   // 2048 u64
    u64*   Ssem   = (u64*)(smx + 20480);   // 693 u64 (21*33)
    float* s_bias = smx + 21888;           // 192

    int t = threadIdx.x, lane = t & 31, wrp = t >> 5;
    int gp0 = blockIdx.x*64;
    int b = gp0 >> 14, pb = gp0 & (NPIX-1);
    int xbase = b*64*NPIX + pb;
    int sbase = b*21*NPIX + pb;

    for (int i=t;i<4096;i+=256){ s_wcat[i]=g_wcat[i]; s_wik[i]=g_wik[i]; s_wiv[i]=g_wiv[i]; }
    if (t<64){ s_bias[t]=g_bcat[t]; s_bias[64+t]=g_bik[t]; s_bias[128+t]=g_biv[t]; }
    for (int i=t;i<2048;i+=256){
        int c=i>>5, pr=i&31;
        R1[c*32 + SWP(c,pr)] = pack2(x[xbase + c*NPIX + pr], x[xbase + c*NPIX + 32 + pr]);
    }
    for (int i=t;i<672;i+=256){
        int kk=i>>5, pr=i&31;
        float s0=sem[sbase+kk*NPIX+pr], s1=sem[sbase+kk*NPIX+32+pr];
        Ssem[kk*33+pr]=pack2(s0>0.f?s0:0.f, s1>0.f?s1:0.f);
    }
    __syncthreads();

    // GEMM-cat: af = sem(cls(o)) * (x@Wcat) + bcat   -> R2 (64 rows)
    u64 acc2[2][4];
    #pragma unroll
    for (int j=0;j<2;j++){ acc2[j][0]=0ull; acc2[j][1]=0ull; acc2[j][2]=0ull; acc2[j][3]=0ull; }
    #pragma unroll 8
    for (int k=0;k<64;k++) GSTEP64(s_wcat, R1, k, k);
    {
        int _g = ((wrp ^ (lane>>1)) & 7) << 2;
        #pragma unroll
        for (int j=0;j<2;j++){
            int o = 2*lane+j;
            int cls = (o<4) ? 0 : ((o-4)/3 + 1);
            u64 bb = pack2(s_bias[o], s_bias[o]);
            #pragma unroll
            for (int p=0;p<4;p++){
                u64 sm = Ssem[cls*33 + 4*wrp + p];
                R2[o*32 + _g + p] = fma2_(sm, acc2[j][p], bb);
            }
        }
    }
    __syncthreads();

    // GEMM-k: k = af @ Wik + bik -> R1 -> writeout
    #pragma unroll
    for (int j=0;j<2;j++){ acc2[j][0]=0ull; acc2[j][1]=0ull; acc2[j][2]=0ull; acc2[j][3]=0ull; }
    #pragma unroll 8
    for (int k=0;k<64;k++) GSTEP64(s_wik, R2, k, k);
    {
        int _g = ((wrp ^ (lane>>1)) & 7) << 2;
        #pragma unroll
        for (int j=0;j<2;j++){
            int o = 2*lane+j;
            u64 bb = pack2(s_bias[64+o], s_bias[64+o]);
            #pragma unroll
            for (int p=0;p<4;p++) R1[o*32 + _g + p] = add2_(acc2[j][p], bb);
        }
    }
    __syncthreads();
    for (int idx=t; idx<2048; idx+=256){
        int o=idx>>5, pr=idx&31;
        float lo,hi; unpack2(R1[o*32+SWP(o,pr)], lo, hi);
        g_k[o*BN + gp0 + pr]      = lo;
        g_k[o*BN + gp0 + 32 + pr] = hi;
    }
    // GEMM-v
    #pragma unroll
    for (int j=0;j<2;j++){ acc2[j][0]=0ull; acc2[j][1]=0ull; acc2[j][2]=0ull; acc2[j][3]=0ull; }
    #pragma unroll 8
    for (int k=0;k<64;k++) GSTEP64(s_wiv, R2, k, k);
    __syncthreads();
    {
        int _g = ((wrp ^ (lane>>1)) & 7) << 2;
        #pragma unroll
        for (int j=0;j<2;j++){
            int o = 2*lane+j;
            u64 bb = pack2(s_bias[128+o], s_bias[128+o]);
            #pragma unroll
            for (int p=0;p<4;p++) R1[o*32 + _g + p] = add2_(acc2[j][p], bb);
        }
    }
    __syncthreads();
    for (int idx=t; idx<2048; idx+=256){
        int o=idx>>5, pr=idx&31;
        float lo,hi; unpack2(R1[o*32+SWP(o,pr)], lo, hi);
        g_v[o*BN + gp0 + pr]      = lo;
        g_v[o*BN + gp0 + 32 + pr] = hi;
    }
}

// ------------ k2: GEMM-tiled LN-MLP -> xm, q ----------------------------------
// smem floats: Wf 8192 | R1 8192 | R2 8192 | s_p 896 | SS 512 | SS2 512 | mP 64 | rP 64
__global__ void __launch_bounds__(256,2)
k2(const float* __restrict__ x,
   const float* __restrict__ w1, const float* __restrict__ b1,
   const float* __restrict__ gm1, const float* __restrict__ be1,
   const float* __restrict__ w2, const float* __restrict__ b2,
   const float* __restrict__ gm2, const float* __restrict__ be2,
   const float* __restrict__ w3, const float* __restrict__ b3,
   const float* __restrict__ wq, const float* __restrict__ bq)
{
    extern __shared__ float smx[];
    float* Wf  = smx;                       // 8192
    u64*   R1  = (u64*)(smx + 8192);        // 4096 u64
    u64*   R2  = (u64*)(smx + 16384);       // 4096 u64
    float* s_p = smx + 24576;               // 896
    u64*   SS  = (u64*)(smx + 25472);       // 256 u64
    u64*   SS2 = (u64*)(smx + 25984);       // 256 u64
    u64*   mP  = (u64*)(smx + 26496);       // 32 u64
    u64*   rP  = (u64*)(smx + 26560);       // 32 u64

    int t = threadIdx.x, lane = t & 31, wrp = t >> 5;
    int gp0 = blockIdx.x*64;
    int b = gp0 >> 14, pb = gp0 & (NPIX-1);
    int xbase = b*64*NPIX + pb;

    if (t < 128){
        s_p[t]=b1[t]; s_p[128+t]=gm1[t]; s_p[256+t]=be1[t];
        s_p[384+t]=b2[t]; s_p[512+t]=gm2[t]; s_p[640+t]=be2[t];
    }
    if (t < 64){ s_p[768+t]=b3[t]; s_p[832+t]=bq[t]; }
    for (int i=t;i<8192;i+=256) Wf[i]=w1[i];
    for (int i=t;i<2048;i+=256){
        int c=i>>5, pr=i&31;
        R1[c*32 + SWP(c,pr)] = pack2(x[xbase + c*NPIX + pr], x[xbase + c*NPIX + 32 + pr]);
    }
    __syncthreads();

    // GEMM1: u1 = x @ w1 + b1 -> R2 (128 rows)
    u64 acc[4][4];
    #pragma unroll
    for (int j=0;j<4;j++){ acc[j][0]=0ull; acc[j][1]=0ull; acc[j][2]=0ull; acc[j][3]=0ull; }
    #pragma unroll 8
    for (int k=0;k<64;k++) GSTEP128(Wf, R1, k, k);
    {
        int _g = ((wrp ^ lane) & 7) << 2;
        #pragma unroll
        for (int j=0;j<4;j++){
            int o = 4*lane+j;
            u64 bb = pack2(s_p[o], s_p[o]);
            #pragma unroll
            for (int p=0;p<4;p++) R2[o*32 + _g + p] = add2_(acc[j][p], bb);
        }
    }
    ln_swz(R2, s_p+128, s_p+256, SS, SS2, mP, rP, t);

    // GEMM2: u2 = h1 @ w2 + b2 -> R1 (two weight halves)
    for (int i=t;i<8192;i+=256) Wf[i]=w2[i];
    __syncthreads();
    #pragma unroll
    for (int j=0;j<4;j++){ acc[j][0]=0ull; acc[j][1]=0ull; acc[j][2]=0ull; acc[j][3]=0ull; }
    #pragma unroll 8
    for (int k=0;k<64;k++) GSTEP128(Wf, R2, k, k);
    __syncthreads();
    for (int i=t;i<8192;i+=256) Wf[i]=w2[8192+i];
    __syncthreads();
    #pragma unroll 8
    for (int k=0;k<64;k++) GSTEP128(Wf, R2, 64+k, k);
    {
        int _g = ((wrp ^ lane) & 7) << 2;
        #pragma unroll
        for (int j=0;j<4;j++){
            int o = 4*lane+j;
            u64 bb = pack2(s_p[384+o], s_p[384+o]);
            #pragma unroll
            for (int p=0;p<4;p++) R1[o*32 + _g + p] = add2_(acc[j][p], bb);
        }
    }
    ln_swz(R1, s_p+512, s_p+640, SS, SS2, mP, rP, t);

    // GEMM3: xm = h2 @ w3 + b3 -> R2 (64 rows) + g_xm
    for (int i=t;i<8192;i+=256) Wf[i]=w3[i];
    __syncthreads();
    u64 acc2[2][4];
    #pragma unroll
    for (int j=0;j<2;j++){ acc2[j][0]=0ull; acc2[j][1]=0ull; acc2[j][2]=0ull; acc2[j][3]=0ull; }
    #pragma unroll 8
    for (int k=0;k<128;k++) GSTEP64(Wf, R1, k, k);
    {
        int _g = ((wrp ^ (lane>>1)) & 7) << 2;
        #pragma unroll
        for (int j=0;j<2;j++){
            int o = 2*lane+j;
            u64 bb = pack2(s_p[768+o], s_p[768+o]);
            #pragma unroll
            for (int p=0;p<4;p++) R2[o*32 + _g + p] = add2_(acc2[j][p], bb);
        }
    }
    __syncthreads();
    for (int idx=t; idx<2048; idx+=256){
        int o=idx>>5, pr=idx&31;
        float lo,hi; unpack2(R2[o*32+SWP(o,pr)], lo, hi);
        g_xm[o*BN + gp0 + pr]      = lo;
        g_xm[o*BN + gp0 + 32 + pr] = hi;
    }
    for (int i=t;i<4096;i+=256) Wf[i]=wq[i];
    __syncthreads();

    // qGEMM: q = xm @ wq + bq -> R1 -> writeout
    #pragma unroll
    for (int j=0;j<2;j++){ acc2[j][0]=0ull; acc2[j][1]=0ull; acc2[j][2]=0ull; acc2[j][3]=0ull; }
    #pragma unroll 8
    for (int k=0;k<64;k++) GSTEP64(Wf, R2, k, k);
    {
        int _g = ((wrp ^ (lane>>1)) & 7) << 2;
        #pragma unroll
        for (int j=0;j<2;j++){
            int o = 2*lane+j;
            u64 bb = pack2(s_p[832+o], s_p[832+o]);
            #pragma unroll
            for (int p=0;p<4;p++) R1[o*32 + _g + p] = add2_(acc2[j][p], bb);
        }
    }
    __syncthreads();
    for (int idx=t; idx<2048; idx+=256){
        int o=idx>>5, pr=idx&31;
        float lo,hi; unpack2(R1[o*32+SWP(o,pr)], lo, hi);
        g_q[o*BN + gp0 + pr]      = lo;
        g_q[o*BN + gp0 + 32 + pr] = hi;
    }
}

// ------------ k3: Gram + norm partials per 128-pixel chunk -------------------
#define CHUNK 128
#define TP 129
__global__ void __launch_bounds__(256,2) k3()
{
    extern __shared__ float smx[];
    float* qs  = smx;
    float* ks  = smx + 64*TP;
    float* red = smx + 128*TP;
    int t = threadIdx.x;
    int chunk = blockIdx.x, b = blockIdx.y;
    int pbase = b*NPIX + chunk*CHUNK;
    for (int i=t; i<64*CHUNK; i+=256){
        int ch=i>>7, pp=i&(CHUNK-1);
        qs[ch*TP+pp]=g_q[ch*BN+pbase+pp];
        ks[ch*TP+pp]=g_k[ch*BN+pbase+pp];
    }
    __syncthreads();
    int sub=t>>6, combo=t&63;
    int h=combo>>4, d4=(combo>>2)&3, e4=combo&3;
    const float* qsb=qs+(h*16+d4*4)*TP;
    const float* ksb=ks+(h*16+e4*4)*TP;
    float acc[4][4];
    #pragma unroll
    for (int i=0;i<4;i++)
        #pragma unroll
        for (int j=0;j<4;j++) acc[i][j]=0.f;
    for (int pp=sub*32; pp<sub*32+32; pp++){
        float q0=qsb[pp],q1=qsb[TP+pp],q2=qsb[2*TP+pp],q3=qsb[3*TP+pp];
        float k0=ksb[pp],k1v=ksb[TP+pp],k2v=ksb[2*TP+pp],k3v=ksb[3*TP+pp];
        acc[0][0]=fmaf(q0,k0,acc[0][0]); acc[0][1]=fmaf(q0,k1v,acc[0][1]); acc[0][2]=fmaf(q0,k2v,acc[0][2]); acc[0][3]=fmaf(q0,k3v,acc[0][3]);
        acc[1][0]=fmaf(q1,k0,acc[1][0]); acc[1][1]=fmaf(q1,k1v,acc[1][1]); acc[1][2]=fmaf(q1,k2v,acc[1][2]); acc[1][3]=fmaf(q1,k3v,acc[1][3]);
        acc[2][0]=fmaf(q2,k0,acc[2][0]); acc[2][1]=fmaf(q2,k1v,acc[2][1]); acc[2][2]=fmaf(q2,k2v,acc[2][2]); acc[2][3]=fmaf(q2,k3v,acc[2][3]);
        acc[3][0]=fmaf(q3,k0,acc[3][0]); acc[3][1]=fmaf(q3,k1v,acc[3][1]); acc[3][2]=fmaf(q3,k2v,acc[3][2]); acc[3][3]=fmaf(q3,k3v,acc[3][3]);
    }
    #pragma unroll
    for (int i=0;i<4;i++)
        #pragma unroll
        for (int j=0;j<4;j++)
            red[sub*1024 + (h*16+d4*4+i)*16 + (e4*4+j)] = acc[i][j];
    if (t < 64){
        const float* qr=qs+t*TP;
        float a0=0,a1=0,a2=0,a3=0;
        for (int pp=0;pp<CHUNK;pp+=4){
            a0=fmaf(qr[pp+0],qr[pp+0],a0); a1=fmaf(qr[pp+1],qr[pp+1],a1);
            a2=fmaf(qr[pp+2],qr[pp+2],a2); a3=fmaf(qr[pp+3],qr[pp+3],a3);
        }
        g_sqp[(b*128+chunk)*64+t]=(a0+a1)+(a2+a3);
    } else if (t < 128){
        int ch=t-64;
        const float* kr=ks+ch*TP;
        float a0=0,a1=0,a2=0,a3=0;
        for (int pp=0;pp<CHUNK;pp+=4){
            a0=fmaf(kr[pp+0],kr[pp+0],a0); a1=fmaf(kr[pp+1],kr[pp+1],a1);
            a2=fmaf(kr[pp+2],kr[pp+2],a2); a3=fmaf(kr[pp+3],kr[pp+3],a3);
        }
        g_skp[(b*128+chunk)*64+ch]=(a0+a1)+(a2+a3);
    }
    __syncthreads();
    float* gout = g_Gpart + (b*128+chunk)*1024;
    for (int idx=t; idx<1024; idx+=256)
        gout[idx] = (red[idx]+red[1024+idx]) + (red[2048+idx]+red[3072+idx]);
}

// ------------ k4: reduce + softmax + fold A into wo --------------------------
__global__ void k4(const float* __restrict__ rescale, const float* __restrict__ wo)
{
    __shared__ float sG[1024];
    __shared__ float snq[64], snk[64];
    __shared__ float sA[1024];
    __shared__ float swo[4096];
    int b=blockIdx.x, t=threadIdx.x;
    {
        float a0=0.f,a1=0.f,a2=0.f,a3=0.f;
        for (int c=0;c<128;c++){
            const float4 v = ((const float4*)(g_Gpart+(b*128+c)*1024))[t];
            a0+=v.x; a1+=v.y; a2+=v.z; a3+=v.w;
        }
        sG[t*4+0]=a0; sG[t*4+1]=a1; sG[t*4+2]=a2; sG[t*4+3]=a3;
    }
    if (t<64){
        float aq=0.f, ak=0.f;
        for (int c=0;c<128;c++){ aq+=g_sqp[(b*128+c)*64+t]; ak+=g_skp[(b*128+c)*64+t]; }
        snq[t]=sqrtf(aq)+1e-8f; snk[t]=sqrtf(ak)+1e-8f;
    }
    for (int i=t;i<4096;i+=256) swo[i]=wo[i];
    __syncthreads();
    if (t<64){
        int h=t>>4;
        float r=rescale[h], nq=snq[t];
        float ev[16]; float mx=-1e30f;
        #pragma unroll
        for (int e=0;e<16;e++){ ev[e]=sG[t*16+e]/(nq*snk[h*16+e])*r; mx=fmaxf(mx,ev[e]); }
        float ss=0.f;
        #pragma unroll
        for (int e=0;e<16;e++){ ev[e]=expf(ev[e]-mx); ss+=ev[e]; }
        float inv=1.f/ss;
        #pragma unroll
        for (int e=0;e<16;e++) sA[t*16+e]=ev[e]*inv;
    }
    __syncthreads();
    for (int idx=t; idx<4096; idx+=256){
        int cp=idx>>6, e=idx&63, h=e>>4, e15=e&15;
        float acc=0.f;
        #pragma unroll
        for (int d=0;d<16;d++)
            acc = fmaf(sA[h*256 + d*16 + e15], swo[(h*16+d)*64 + cp], acc);
        g_weff[b*4096 + e*64 + cp] = acc;
    }
}

// ------------ k5: out = v @ Weff + bo + xm (GEMM tiles) -----------------------
// smem floats: s_w 4096 | R1 4096 | R2 4096 | sbo 64 = 12352
__global__ void __launch_bounds__(256,4)
k5(const float* __restrict__ bo, float* __restrict__ out)
{
    extern __shared__ float smx[];
    float* s_w = smx;                     // 4096 (Weff [e][cp])
    u64*   R1  = (u64*)(smx + 4096);      // 2048 u64
    u64*   R2  = (u64*)(smx + 8192);      // 2048 u64
    float* sbo = smx + 12288;             // 64

    int t = threadIdx.x, lane = t & 31, wrp = t >> 5;
    int gp0 = blockIdx.x*64;
    int b = gp0 >> 14, pb = gp0 & (NPIX-1);

    for (int i=t;i<4096;i+=256) s_w[i]=g_weff[b*4096+i];
    if (t<64) sbo[t]=bo[t];
    for (int i=t;i<2048;i+=256){
        int e=i>>5, pr=i&31;
        R1[e*32 + SWP(e,pr)] = pack2(g_v[e*BN + gp0 + pr], g_v[e*BN + gp0 + 32 + pr]);
    }
    __syncthreads();

    u64 acc2[2][4];
    #pragma unroll
    for (int j=0;j<2;j++){ acc2[j][0]=0ull; acc2[j][1]=0ull; acc2[j][2]=0ull; acc2[j][3]=0ull; }
    #pragma unroll 8
    for (int k=0;k<64;k++) GSTEP64(s_w, R1, k, k);
    {
        int _g = ((wrp ^ (lane>>1)) & 7) << 2;
        #pragma unroll
        for (int j=0;j<2;j++){
            int o = 2*lane+j;
            #pragma unroll
            for (int p=0;p<4;p++) R2[o*32 + _g + p] = acc2[j][p];
        }
    }
    __syncthreads();
    for (int idx=t; idx<2048; idx+=256){
        int o=idx>>5, pr=idx&31;
        float lo,hi; unpack2(R2[o*32+SWP(o,pr)], lo, hi);
        size_t row = (size_t)(b*64+o)*NPIX;
        out[row + pb + pr]      = lo + sbo[o] + g_xm[o*BN + gp0 + pr];
        out[row + pb + 32 + pr] = hi + sbo[o] + g_xm[o*BN + gp0 + 32 + pr];
    }
}

// ------------ launch ----------------------------------------------------------
extern "C" void kernel_launch(void* const* d_in, const int* in_sizes, int n_in,
                              void* d_out, int out_size)
{
    const float* x   =(const float*)d_in[0];
    const float* sem =(const float*)d_in[1];
    const float* wa  =(const float*)d_in[2];
    const float* ba  =(const float*)d_in[3];
    const float* wb  =(const float*)d_in[4];
    const float* bb  =(const float*)d_in[5];
    const float* inw =(const float*)d_in[6];
    const float* inb =(const float*)d_in[7];
    const float* w1  =(const float*)d_in[8];
    const float* b1  =(const float*)d_in[9];
    const float* gm1 =(const float*)d_in[10];
    const float* be1 =(const float*)d_in[11];
    const float* w2  =(const float*)d_in[12];
    const float* b2  =(const float*)d_in[13];
    const float* gm2 =(const float*)d_in[14];
    const float* be2 =(const float*)d_in[15];
    const float* w3  =(const float*)d_in[16];
    const float* b3  =(const float*)d_in[17];
    const float* wq  =(const float*)d_in[18];
    const float* bq  =(const float*)d_in[19];
    const float* wk  =(const float*)d_in[20];
    const float* bk  =(const float*)d_in[21];
    const float* wv  =(const float*)d_in[22];
    const float* bv  =(const float*)d_in[23];
    const float* wo  =(const float*)d_in[24];
    const float* bo  =(const float*)d_in[25];
    const float* rescale=(const float*)d_in[26];
    float* out=(float*)d_out;

    cudaFuncSetAttribute(k1, cudaFuncAttributeMaxDynamicSharedMemorySize, 22080*4);
    cudaFuncSetAttribute(k2, cudaFuncAttributeMaxDynamicSharedMemorySize, 26624*4);
    cudaFuncSetAttribute(k3, cudaFuncAttributeMaxDynamicSharedMemorySize, (128*TP+4096)*4);
    cudaFuncSetAttribute(k5, cudaFuncAttributeMaxDynamicSharedMemorySize, 12352*4);

    kprep<<<16,256>>>(wa,ba,wb,bb);
    kfold<<<32,256>>>(inw,inb,wk,bk,wv,bv);
    k1<<<1024,256,22080*4>>>(x,sem);
    k2<<<1024,256,26624*4>>>(x,w1,b1,gm1,be1,w2,b2,gm2,be2,w3,b3,wq,bq);
    k3<<<dim3(128,4),256,(128*TP+4096)*4>>>();
    k4<<<4,256>>>(rescale,wo);
    k5<<<1024,256,12352*4>>>(bo,out);
}

// round 12
// speedup vs baseline: 1.3705x; 1.0339x over previous
#include <cuda_runtime.h>
#include <math.h>

#define NPIX 16384
#define BN   65536   // 4 * 16384

typedef unsigned long long u64;

// ------------ scratch ------------------------------------------------------
__device__ float g_k[64*BN];
__device__ float g_v[64*BN];
__device__ float g_q[64*BN];
__device__ float g_xm[64*BN];
__device__ float g_Gpart[4*128*1024];
__device__ float g_sqp[4*128*64];
__device__ float g_skp[4*128*64];
__device__ float g_weff[4*4096];     // [b][e*64+cp]
__device__ float g_wcat[4096];       // [c][j]
__device__ float g_wik[4096];        // (in_w@wk) [c][o]
__device__ float g_wiv[4096];        // (in_w@wv) [c][o]
__device__ float g_bcat[64];
__device__ float g_bik[64];
__device__ float g_biv[64];

// ------------ f32x2 helpers (k1/k5) -----------------------------------------
__device__ __forceinline__ u64 pack2(float lo, float hi){
    u64 r; asm("mov.b64 %0, {%1,%2};" : "=l"(r) : "f"(lo), "f"(hi)); return r;
}
__device__ __forceinline__ void unpack2(u64 a, float& lo, float& hi){
    asm("mov.b64 {%0,%1}, %2;" : "=f"(lo), "=f"(hi) : "l"(a));
}
__device__ __forceinline__ u64 fma2_(u64 a, u64 b, u64 c){
    u64 d; asm("fma.rn.f32x2 %0, %1, %2, %3;" : "=l"(d) : "l"(a), "l"(b), "l"(c)); return d;
}
__device__ __forceinline__ u64 add2_(u64 a, u64 b){
    u64 d; asm("add.rn.f32x2 %0, %1, %2;" : "=l"(d) : "l"(a), "l"(b)); return d;
}
__device__ __forceinline__ int SWP(int o, int p){
    return (p & 3) | ((((p >> 2) ^ (o >> 2)) & 7) << 2);
}

#define GSTEP64(W, R, RROW, KK) do{ \
    const float2 _wv = *(const float2*)((W)+(KK)*64+2*lane); \
    int _g = (((wrp)^((RROW)>>2))&7)<<2; \
    const ulonglong2 _xa = *(const ulonglong2*)((R)+(RROW)*32+_g); \
    const ulonglong2 _xb = *(const ulonglong2*)((R)+(RROW)*32+_g+2); \
    u64 _w0=pack2(_wv.x,_wv.x), _w1=pack2(_wv.y,_wv.y); \
    acc2[0][0]=fma2_(_xa.x,_w0,acc2[0][0]); acc2[0][1]=fma2_(_xa.y,_w0,acc2[0][1]); acc2[0][2]=fma2_(_xb.x,_w0,acc2[0][2]); acc2[0][3]=fma2_(_xb.y,_w0,acc2[0][3]); \
    acc2[1][0]=fma2_(_xa.x,_w1,acc2[1][0]); acc2[1][1]=fma2_(_xa.y,_w1,acc2[1][1]); acc2[1][2]=fma2_(_xb.x,_w1,acc2[1][2]); acc2[1][3]=fma2_(_xb.y,_w1,acc2[1][3]); \
}while(0)

// ------------ tf32 mma helpers -----------------------------------------------
__device__ __forceinline__ float tf32f(float x){
    unsigned u; asm("cvt.rna.tf32.f32 %0, %1;" : "=r"(u) : "f"(x));
    return __uint_as_float(u);
}
#define MMA_TF32(D, A0,A1,A2,A3, B0,B1) \
    asm volatile("mma.sync.aligned.m16n8k8.row.col.f32.tf32.tf32.f32 " \
        "{%0,%1,%2,%3},{%4,%5,%6,%7},{%8,%9},{%0,%1,%2,%3};" \
        : "+f"(D[0]),"+f"(D[1]),"+f"(D[2]),"+f"(D[3]) \
        : "r"(A0),"r"(A1),"r"(A2),"r"(A3),"r"(B0),"r"(B1))

// ------------ kprep / kfold --------------------------------------------------
__global__ void kprep(const float* wa, const float* ba, const float* wb, const float* bb)
{
    int t = blockIdx.x*256 + threadIdx.x;
    if (t < 4096){
        int c = t>>6, j = t&63;
        float w;
        if (j < 4) w = wa[c*4 + j];
        else { int u=j-4; int kk=u/3; int d=u-kk*3; w = wb[kk*192 + c*3 + d]; }
        g_wcat[t] = w;
    }
    if (t < 64) g_bcat[t] = (t < 4) ? ba[t] : bb[t-4];
}

__global__ void kfold(const float* inw, const float* inb,
                      const float* wk, const float* bk,
                      const float* wv, const float* bv)
{
    int t = blockIdx.x*256 + threadIdx.x;
    int c = (t>>6)&63, o = t&63;
    const float* wx = (t < 4096) ? wk : wv;
    float acc = 0.f;
    #pragma unroll 4
    for (int m=0;m<64;m++) acc = fmaf(inw[c*64+m], wx[m*64+o], acc);
    if (t < 4096) g_wik[c*64+o] = acc;
    else          g_wiv[c*64+o] = acc;
    if (t < 64){
        float a=0.f, b2=0.f;
        for (int m=0;m<64;m++){ a=fmaf(inb[m],wk[m*64+t],a); b2=fmaf(inb[m],wv[m*64+t],b2); }
        g_bik[t] = a + bk[t];
        g_biv[t] = b2 + bv[t];
    }
}

// ------------ k1: feat path -> k, v (R11 champion) ---------------------------
__global__ void __launch_bounds__(256,2)
k1(const float* __restrict__ x, const float* __restrict__ sem)
{
    extern __shared__ float smx[];
    float* s_wcat = smx;
    float* s_wik  = smx + 4096;
    float* s_wiv  = smx + 8192;
    u64*   R1     = (u64*)(smx + 12288);
    u64*   R2     = (u64*)(smx + 16384);
    u64*   Ssem   = (u64*)(smx + 20480);
    float* s_bias = smx + 21888;

    int t = threadIdx.x, lane = t & 31, wrp = t >> 5;
    int gp0 = blockIdx.x*64;
    int b = gp0 >> 14, pb = gp0 & (NPIX-1);
    int xbase = b*64*NPIX + pb;
    int sbase = b*21*NPIX + pb;

    for (int i=t;i<4096;i+=256){ s_wcat[i]=g_wcat[i]; s_wik[i]=g_wik[i]; s_wiv[i]=g_wiv[i]; }
    if (t<64){ s_bias[t]=g_bcat[t]; s_bias[64+t]=g_bik[t]; s_bias[128+t]=g_biv[t]; }
    for (int i=t;i<2048;i+=256){
        int c=i>>5, pr=i&31;
        R1[c*32 + SWP(c,pr)] = pack2(x[xbase + c*NPIX + pr], x[xbase + c*NPIX + 32 + pr]);
    }
    for (int i=t;i<672;i+=256){
        int kk=i>>5, pr=i&31;
        float s0=sem[sbase+kk*NPIX+pr], s1=sem[sbase+kk*NPIX+32+pr];
        Ssem[kk*33+pr]=pack2(s0>0.f?s0:0.f, s1>0.f?s1:0.f);
    }
    __syncthreads();

    u64 acc2[2][4];
    #pragma unroll
    for (int j=0;j<2;j++){ acc2[j][0]=0ull; acc2[j][1]=0ull; acc2[j][2]=0ull; acc2[j][3]=0ull; }
    #pragma unroll 8
    for (int k=0;k<64;k++) GSTEP64(s_wcat, R1, k, k);
    {
        int _g = ((wrp ^ (lane>>1)) & 7) << 2;
        #pragma unroll
        for (int j=0;j<2;j++){
            int o = 2*lane+j;
            int cls = (o<4) ? 0 : ((o-4)/3 + 1);
            u64 bb = pack2(s_bias[o], s_bias[o]);
            #pragma unroll
            for (int p=0;p<4;p++){
                u64 sm = Ssem[cls*33 + 4*wrp + p];
                R2[o*32 + _g + p] = fma2_(sm, acc2[j][p], bb);
            }
        }
    }
    __syncthreads();

    #pragma unroll
    for (int j=0;j<2;j++){ acc2[j][0]=0ull; acc2[j][1]=0ull; acc2[j][2]=0ull; acc2[j][3]=0ull; }
    #pragma unroll 8
    for (int k=0;k<64;k++) GSTEP64(s_wik, R2, k, k);
    {
        int _g = ((wrp ^ (lane>>1)) & 7) << 2;
        #pragma unroll
        for (int j=0;j<2;j++){
            int o = 2*lane+j;
            u64 bb = pack2(s_bias[64+o], s_bias[64+o]);
            #pragma unroll
            for (int p=0;p<4;p++) R1[o*32 + _g + p] = add2_(acc2[j][p], bb);
        }
    }
    __syncthreads();
    for (int idx=t; idx<2048; idx+=256){
        int o=idx>>5, pr=idx&31;
        float lo,hi; unpack2(R1[o*32+SWP(o,pr)], lo, hi);
        g_k[o*BN + gp0 + pr]      = lo;
        g_k[o*BN + gp0 + 32 + pr] = hi;
    }
    #pragma unroll
    for (int j=0;j<2;j++){ acc2[j][0]=0ull; acc2[j][1]=0ull; acc2[j][2]=0ull; acc2[j][3]=0ull; }
    #pragma unroll 8
    for (int k=0;k<64;k++) GSTEP64(s_wiv, R2, k, k);
    __syncthreads();
    {
        int _g = ((wrp ^ (lane>>1)) & 7) << 2;
        #pragma unroll
        for (int j=0;j<2;j++){
            int o = 2*lane+j;
            u64 bb = pack2(s_bias[128+o], s_bias[128+o]);
            #pragma unroll
            for (int p=0;p<4;p++) R1[o*32 + _g + p] = add2_(acc2[j][p], bb);
        }
    }
    __syncthreads();
    for (int idx=t; idx<2048; idx+=256){
        int o=idx>>5, pr=idx&31;
        float lo,hi; unpack2(R1[o*32+SWP(o,pr)], lo, hi);
        g_v[o*BN + gp0 + pr]      = lo;
        g_v[o*BN + gp0 + 32 + pr] = hi;
    }
}

// ------------ k2: tf32 tensor-core LN-MLP -> xm, q ----------------------------
// smem floats: Xs 64x66 | Us 64x130 | Ws 64x136 | s_p 896 | SSm 256 | SSq 256 | s_m 64 | s_r 64
#define XS_ST 66
#define US_ST 130
#define WS_ST 136
#define W3_ST 72

__device__ __forceinline__ void ln_tile(float* Us, const float* g, const float* be,
    float* SSm, float* SSq, float* s_m, float* s_r, int t)
{
    int px = t&63, part = t>>6;
    float s=0.f, s2=0.f;
    const float* rp = Us + px*US_ST + part*32;
    #pragma unroll 8
    for (int i=0;i<32;i++){ float v=rp[i]; s+=v; s2=fmaf(v,v,s2); }
    SSm[part*64+px]=s; SSq[part*64+px]=s2;
    __syncthreads();
    if (t<64){
        float a =SSm[t]+SSm[64+t]+SSm[128+t]+SSm[192+t];
        float a2=SSq[t]+SSq[64+t]+SSq[128+t]+SSq[192+t];
        float m=a*(1.f/128.f);
        s_m[t]=m; s_r[t]=rsqrtf(a2*(1.f/128.f)-m*m+1e-5f);
    }
    __syncthreads();
    #pragma unroll 4
    for (int idx=t; idx<8192; idx+=256){
        int px2=idx>>7, o=idx&127;
        float h=(Us[px2*US_ST+o]-s_m[px2])*s_r[px2]*g[o]+be[o];
        h = h>0.f?h:0.01f*h;
        Us[px2*US_ST+o]=tf32f(h);
    }
    __syncthreads();
}

__global__ void __launch_bounds__(256,2)
k2(const float* __restrict__ x,
   const float* __restrict__ w1, const float* __restrict__ b1,
   const float* __restrict__ gm1, const float* __restrict__ be1,
   const float* __restrict__ w2, const float* __restrict__ b2,
   const float* __restrict__ gm2, const float* __restrict__ be2,
   const float* __restrict__ w3, const float* __restrict__ b3,
   const float* __restrict__ wq, const float* __restrict__ bq)
{
    extern __shared__ float smx[];
    float* Xs  = smx;            // 4224
    float* Us  = smx + 4224;     // 8320
    float* Ws  = smx + 12544;    // 8704
    float* s_p = smx + 21248;    // 896
    float* SSm = smx + 22144;    // 256
    float* SSq = smx + 22400;    // 256
    float* s_m = smx + 22656;    // 64
    float* s_r = smx + 22720;    // 64

    int t = threadIdx.x, lane = t&31, wrp = t>>5;
    int gid = lane>>2, tid = lane&3;
    int px0 = (wrp&3)*16, oA = (wrp>>2)*64, oB = (wrp>>2)*32;
    int gp0 = blockIdx.x*64;
    int b = gp0>>14, pb = gp0 & (NPIX-1);
    int xbase = b*64*NPIX + pb;

    if (t<128){ s_p[t]=b1[t]; s_p[128+t]=gm1[t]; s_p[256+t]=be1[t];
                s_p[384+t]=b2[t]; s_p[512+t]=gm2[t]; s_p[640+t]=be2[t]; }
    if (t<64){ s_p[768+t]=b3[t]; s_p[832+t]=bq[t]; }
    for (int i=t;i<4096;i+=256){
        int c=i>>6, px=i&63;
        Xs[px*XS_ST+c] = tf32f(x[xbase + c*NPIX + px]);
    }
    for (int i=t;i<8192;i+=256) Ws[(i>>7)*WS_ST + (i&127)] = tf32f(w1[i]);
    __syncthreads();

    // ---- GEMM1: u1 = x @ w1 + b1 ----
    float D[8][4];
    #pragma unroll
    for (int nb=0;nb<8;nb++){ D[nb][0]=0.f; D[nb][1]=0.f; D[nb][2]=0.f; D[nb][3]=0.f; }
    {
        unsigned a[8][4];
        const float* A0 = Xs + (px0+gid)*XS_ST + tid;
        const float* A1 = A0 + 8*XS_ST;
        #pragma unroll
        for (int kg=0;kg<8;kg++){
            a[kg][0]=__float_as_uint(A0[kg*8]);
            a[kg][1]=__float_as_uint(A1[kg*8]);
            a[kg][2]=__float_as_uint(A0[kg*8+4]);
            a[kg][3]=__float_as_uint(A1[kg*8+4]);
        }
        #pragma unroll
        for (int nb=0;nb<8;nb++){
            const float* Bp = Ws + tid*WS_ST + oA + nb*8 + gid;
            #pragma unroll
            for (int kg=0;kg<8;kg++){
                unsigned b0=__float_as_uint(Bp[kg*8*WS_ST]);
                unsigned b1=__float_as_uint(Bp[kg*8*WS_ST + 4*WS_ST]);
                MMA_TF32(D[nb], a[kg][0],a[kg][1],a[kg][2],a[kg][3], b0,b1);
            }
        }
    }
    #pragma unroll
    for (int nb=0;nb<8;nb++){
        int n0 = oA + nb*8 + 2*tid;
        float bb0=s_p[n0], bb1=s_p[n0+1];
        *(float2*)&Us[(px0+gid)*US_ST+n0]   = make_float2(D[nb][0]+bb0, D[nb][1]+bb1);
        *(float2*)&Us[(px0+gid+8)*US_ST+n0] = make_float2(D[nb][2]+bb0, D[nb][3]+bb1);
    }
    __syncthreads();
    ln_tile(Us, s_p+128, s_p+256, SSm, SSq, s_m, s_r, t);

    // ---- GEMM2: u2 = h1 @ w2 + b2 (K=128, two staged halves) ----
    for (int i=t;i<8192;i+=256) Ws[(i>>7)*WS_ST+(i&127)] = tf32f(w2[i]);
    __syncthreads();
    #pragma unroll
    for (int nb=0;nb<8;nb++){ D[nb][0]=0.f; D[nb][1]=0.f; D[nb][2]=0.f; D[nb][3]=0.f; }
    #pragma unroll
    for (int half=0; half<2; half++){
        unsigned a[8][4];
        const float* A0 = Us + (px0+gid)*US_ST + half*64 + tid;
        const float* A1 = A0 + 8*US_ST;
        #pragma unroll
        for (int kg=0;kg<8;kg++){
            a[kg][0]=__float_as_uint(A0[kg*8]);
            a[kg][1]=__float_as_uint(A1[kg*8]);
            a[kg][2]=__float_as_uint(A0[kg*8+4]);
            a[kg][3]=__float_as_uint(A1[kg*8+4]);
        }
        #pragma unroll
        for (int nb=0;nb<8;nb++){
            const float* Bp = Ws + tid*WS_ST + oA + nb*8 + gid;
            #pragma unroll
            for (int kg=0;kg<8;kg++){
                unsigned b0=__float_as_uint(Bp[kg*8*WS_ST]);
                unsigned b1=__float_as_uint(Bp[kg*8*WS_ST+4*WS_ST]);
                MMA_TF32(D[nb], a[kg][0],a[kg][1],a[kg][2],a[kg][3], b0,b1);
            }
        }
        __syncthreads();
        if (half==0){
            for (int i=t;i<8192;i+=256) Ws[(i>>7)*WS_ST+(i&127)] = tf32f(w2[8192+i]);
            __syncthreads();
        }
    }
    #pragma unroll
    for (int nb=0;nb<8;nb++){
        int n0 = oA + nb*8 + 2*tid;
        float bb0=s_p[384+n0], bb1=s_p[384+n0+1];
        *(float2*)&Us[(px0+gid)*US_ST+n0]   = make_float2(D[nb][0]+bb0, D[nb][1]+bb1);
        *(float2*)&Us[(px0+gid+8)*US_ST+n0] = make_float2(D[nb][2]+bb0, D[nb][3]+bb1);
    }
    __syncthreads();
    ln_tile(Us, s_p+512, s_p+640, SSm, SSq, s_m, s_r, t);

    // ---- GEMM3: xm = h2 @ w3 + b3 (K=128, N=64, two staged halves) ----
    for (int i=t;i<4096;i+=256) Ws[(i>>6)*W3_ST+(i&63)] = tf32f(w3[i]);
    __syncthreads();
    float D3[4][4];
    #pragma unroll
    for (int nb=0;nb<4;nb++){ D3[nb][0]=0.f; D3[nb][1]=0.f; D3[nb][2]=0.f; D3[nb][3]=0.f; }
    #pragma unroll
    for (int half=0; half<2; half++){
        unsigned a[8][4];
        const float* A0 = Us + (px0+gid)*US_ST + half*64 + tid;
        const float* A1 = A0 + 8*US_ST;
        #pragma unroll
        for (int kg=0;kg<8;kg++){
            a[kg][0]=__float_as_uint(A0[kg*8]);
            a[kg][1]=__float_as_uint(A1[kg*8]);
            a[kg][2]=__float_as_uint(A0[kg*8+4]);
            a[kg][3]=__float_as_uint(A1[kg*8+4]);
        }
        #pragma unroll
        for (int nb=0;nb<4;nb++){
            const float* Bp = Ws + tid*W3_ST + oB + nb*8 + gid;
            #pragma unroll
            for (int kg=0;kg<8;kg++){
                unsigned b0=__float_as_uint(Bp[kg*8*W3_ST]);
                unsigned b1=__float_as_uint(Bp[kg*8*W3_ST+4*W3_ST]);
                MMA_TF32(D3[nb], a[kg][0],a[kg][1],a[kg][2],a[kg][3], b0,b1);
            }
        }
        __syncthreads();
        if (half==0){
            for (int i=t;i<4096;i+=256) Ws[(i>>6)*W3_ST+(i&63)] = tf32f(w3[4096+i]);
            __syncthreads();
        }
    }
    // store xm (fp32) into Us cols 0..63
    #pragma unroll
    for (int nb=0;nb<4;nb++){
        int n0 = oB + nb*8 + 2*tid;
        float bb0=s_p[768+n0], bb1=s_p[768+n0+1];
        *(float2*)&Us[(px0+gid)*US_ST+n0]   = make_float2(D3[nb][0]+bb0, D3[nb][1]+bb1);
        *(float2*)&Us[(px0+gid+8)*US_ST+n0] = make_float2(D3[nb][2]+bb0, D3[nb][3]+bb1);
    }
    for (int i=t;i<4096;i+=256) Ws[(i>>6)*W3_ST+(i&63)] = tf32f(wq[i]);
    __syncthreads();
    // xm sweep: write g_xm (fp32) and Xs (tf32) for q-GEMM
    for (int idx=t; idx<4096; idx+=256){
        int px2=idx&63, o=idx>>6;
        float v = Us[px2*US_ST+o];
        g_xm[o*BN + gp0 + px2] = v;
        Xs[px2*XS_ST+o] = tf32f(v);
    }
    __syncthreads();

    // ---- q-GEMM: q = xm @ wq + bq (K=64, N=64) ----
    float Dq[4][4];
    #pragma unroll
    for (int nb=0;nb<4;nb++){ Dq[nb][0]=0.f; Dq[nb][1]=0.f; Dq[nb][2]=0.f; Dq[nb][3]=0.f; }
    {
        unsigned a[8][4];
        const float* A0 = Xs + (px0+gid)*XS_ST + tid;
        const float* A1 = A0 + 8*XS_ST;
        #pragma unroll
        for (int kg=0;kg<8;kg++){
            a[kg][0]=__float_as_uint(A0[kg*8]);
            a[kg][1]=__float_as_uint(A1[kg*8]);
            a[kg][2]=__float_as_uint(A0[kg*8+4]);
            a[kg][3]=__float_as_uint(A1[kg*8+4]);
        }
        #pragma unroll
        for (int nb=0;nb<4;nb++){
            const float* Bp = Ws + tid*W3_ST + oB + nb*8 + gid;
            #pragma unroll
            for (int kg=0;kg<8;kg++){
                unsigned b0=__float_as_uint(Bp[kg*8*W3_ST]);
                unsigned b1=__float_as_uint(Bp[kg*8*W3_ST+4*W3_ST]);
                MMA_TF32(Dq[nb], a[kg][0],a[kg][1],a[kg][2],a[kg][3], b0,b1);
            }
        }
    }
    __syncthreads();
    #pragma unroll
    for (int nb=0;nb<4;nb++){
        int n0 = oB + nb*8 + 2*tid;
        float bb0=s_p[832+n0], bb1=s_p[832+n0+1];
        *(float2*)&Us[(px0+gid)*US_ST+n0]   = make_float2(Dq[nb][0]+bb0, Dq[nb][1]+bb1);
        *(float2*)&Us[(px0+gid+8)*US_ST+n0] = make_float2(Dq[nb][2]+bb0, Dq[nb][3]+bb1);
    }
    __syncthreads();
    for (int idx=t; idx<4096; idx+=256){
        int px2=idx&63, o=idx>>6;
        g_q[o*BN + gp0 + px2] = Us[px2*US_ST+o];
    }
}

// ------------ k3: Gram + norm partials per 128-pixel chunk -------------------
#define CHUNK 128
#define TP 129
__global__ void __launch_bounds__(256,2) k3()
{
    extern __shared__ float smx[];
    float* qs  = smx;
    float* ks  = smx + 64*TP;
    float* red = smx + 128*TP;
    int t = threadIdx.x;
    int chunk = blockIdx.x, b = blockIdx.y;
    int pbase = b*NPIX + chunk*CHUNK;
    for (int i=t; i<64*CHUNK; i+=256){
        int ch=i>>7, pp=i&(CHUNK-1);
        qs[ch*TP+pp]=g_q[ch*BN+pbase+pp];
        ks[ch*TP+pp]=g_k[ch*BN+pbase+pp];
    }
    __syncthreads();
    int sub=t>>6, combo=t&63;
    int h=combo>>4, d4=(combo>>2)&3, e4=combo&3;
    const float* qsb=qs+(h*16+d4*4)*TP;
    const float* ksb=ks+(h*16+e4*4)*TP;
    float acc[4][4];
    #pragma unroll
    for (int i=0;i<4;i++)
        #pragma unroll
        for (int j=0;j<4;j++) acc[i][j]=0.f;
    for (int pp=sub*32; pp<sub*32+32; pp++){
        float q0=qsb[pp],q1=qsb[TP+pp],q2=qsb[2*TP+pp],q3=qsb[3*TP+pp];
        float k0=ksb[pp],k1v=ksb[TP+pp],k2v=ksb[2*TP+pp],k3v=ksb[3*TP+pp];
        acc[0][0]=fmaf(q0,k0,acc[0][0]); acc[0][1]=fmaf(q0,k1v,acc[0][1]); acc[0][2]=fmaf(q0,k2v,acc[0][2]); acc[0][3]=fmaf(q0,k3v,acc[0][3]);
        acc[1][0]=fmaf(q1,k0,acc[1][0]); acc[1][1]=fmaf(q1,k1v,acc[1][1]); acc[1][2]=fmaf(q1,k2v,acc[1][2]); acc[1][3]=fmaf(q1,k3v,acc[1][3]);
        acc[2][0]=fmaf(q2,k0,acc[2][0]); acc[2][1]=fmaf(q2,k1v,acc[2][1]); acc[2][2]=fmaf(q2,k2v,acc[2][2]); acc[2][3]=fmaf(q2,k3v,acc[2][3]);
        acc[3][0]=fmaf(q3,k0,acc[3][0]); acc[3][1]=fmaf(q3,k1v,acc[3][1]); acc[3][2]=fmaf(q3,k2v,acc[3][2]); acc[3][3]=fmaf(q3,k3v,acc[3][3]);
    }
    #pragma unroll
    for (int i=0;i<4;i++)
        #pragma unroll
        for (int j=0;j<4;j++)
            red[sub*1024 + (h*16+d4*4+i)*16 + (e4*4+j)] = acc[i][j];
    if (t < 64){
        const float* qr=qs+t*TP;
        float a0=0,a1=0,a2=0,a3=0;
        for (int pp=0;pp<CHUNK;pp+=4){
            a0=fmaf(qr[pp+0],qr[pp+0],a0); a1=fmaf(qr[pp+1],qr[pp+1],a1);
            a2=fmaf(qr[pp+2],qr[pp+2],a2); a3=fmaf(qr[pp+3],qr[pp+3],a3);
        }
        g_sqp[(b*128+chunk)*64+t]=(a0+a1)+(a2+a3);
    } else if (t < 128){
        int ch=t-64;
        const float* kr=ks+ch*TP;
        float a0=0,a1=0,a2=0,a3=0;
        for (int pp=0;pp<CHUNK;pp+=4){
            a0=fmaf(kr[pp+0],kr[pp+0],a0); a1=fmaf(kr[pp+1],kr[pp+1],a1);
            a2=fmaf(kr[pp+2],kr[pp+2],a2); a3=fmaf(kr[pp+3],kr[pp+3],a3);
        }
        g_skp[(b*128+chunk)*64+ch]=(a0+a1)+(a2+a3);
    }
    __syncthreads();
    float* gout = g_Gpart + (b*128+chunk)*1024;
    for (int idx=t; idx<1024; idx+=256)
        gout[idx] = (red[idx]+red[1024+idx]) + (red[2048+idx]+red[3072+idx]);
}

// ------------ k4: reduce + softmax + fold A into wo --------------------------
__global__ void k4(const float* __restrict__ rescale, const float* __restrict__ wo)
{
    __shared__ float sG[1024];
    __shared__ float snq[64], snk[64];
    __shared__ float sA[1024];
    __shared__ float swo[4096];
    int b=blockIdx.x, t=threadIdx.x;
    {
        float a0=0.f,a1=0.f,a2=0.f,a3=0.f;
        for (int c=0;c<128;c++){
            const float4 v = ((const float4*)(g_Gpart+(b*128+c)*1024))[t];
            a0+=v.x; a1+=v.y; a2+=v.z; a3+=v.w;
        }
        sG[t*4+0]=a0; sG[t*4+1]=a1; sG[t*4+2]=a2; sG[t*4+3]=a3;
    }
    if (t<64){
        float aq=0.f, ak=0.f;
        for (int c=0;c<128;c++){ aq+=g_sqp[(b*128+c)*64+t]; ak+=g_skp[(b*128+c)*64+t]; }
        snq[t]=sqrtf(aq)+1e-8f; snk[t]=sqrtf(ak)+1e-8f;
    }
    for (int i=t;i<4096;i+=256) swo[i]=wo[i];
    __syncthreads();
    if (t<64){
        int h=t>>4;
        float r=rescale[h], nq=snq[t];
        float ev[16]; float mx=-1e30f;
        #pragma unroll
        for (int e=0;e<16;e++){ ev[e]=sG[t*16+e]/(nq*snk[h*16+e])*r; mx=fmaxf(mx,ev[e]); }
        float ss=0.f;
        #pragma unroll
        for (int e=0;e<16;e++){ ev[e]=expf(ev[e]-mx); ss+=ev[e]; }
        float inv=1.f/ss;
        #pragma unroll
        for (int e=0;e<16;e++) sA[t*16+e]=ev[e]*inv;
    }
    __syncthreads();
    for (int idx=t; idx<4096; idx+=256){
        int cp=idx>>6, e=idx&63, h=e>>4, e15=e&15;
        float acc=0.f;
        #pragma unroll
        for (int d=0;d<16;d++)
            acc = fmaf(sA[h*256 + d*16 + e15], swo[(h*16+d)*64 + cp], acc);
        g_weff[b*4096 + e*64 + cp] = acc;
    }
}

// ------------ k5: out = v @ Weff + bo + xm (R11 champion) ---------------------
__global__ void __launch_bounds__(256,4)
k5(const float* __restrict__ bo, float* __restrict__ out)
{
    extern __shared__ float smx[];
    float* s_w = smx;
    u64*   R1  = (u64*)(smx + 4096);
    u64*   R2  = (u64*)(smx + 8192);
    float* sbo = smx + 12288;

    int t = threadIdx.x, lane = t & 31, wrp = t >> 5;
    int gp0 = blockIdx.x*64;
    int b = gp0 >> 14, pb = gp0 & (NPIX-1);

    for (int i=t;i<4096;i+=256) s_w[i]=g_weff[b*4096+i];
    if (t<64) sbo[t]=bo[t];
    for (int i=t;i<2048;i+=256){
        int e=i>>5, pr=i&31;
        R1[e*32 + SWP(e,pr)] = pack2(g_v[e*BN + gp0 + pr], g_v[e*BN + gp0 + 32 + pr]);
    }
    __syncthreads();

    u64 acc2[2][4];
    #pragma unroll
    for (int j=0;j<2;j++){ acc2[j][0]=0ull; acc2[j][1]=0ull; acc2[j][2]=0ull; acc2[j][3]=0ull; }
    #pragma unroll 8
    for (int k=0;k<64;k++) GSTEP64(s_w, R1, k, k);
    {
        int _g = ((wrp ^ (lane>>1)) & 7) << 2;
        #pragma unroll
        for (int j=0;j<2;j++){
            int o = 2*lane+j;
            #pragma unroll
            for (int p=0;p<4;p++) R2[o*32 + _g + p] = acc2[j][p];
        }
    }
    __syncthreads();
    for (int idx=t; idx<2048; idx+=256){
        int o=idx>>5, pr=idx&31;
        float lo,hi; unpack2(R2[o*32+SWP(o,pr)], lo, hi);
        size_t row = (size_t)(b*64+o)*NPIX;
        out[row + pb + pr]      = lo + sbo[o] + g_xm[o*BN + gp0 + pr];
        out[row + pb + 32 + pr] = hi + sbo[o] + g_xm[o*BN + gp0 + 32 + pr];
    }
}

// ------------ launch ----------------------------------------------------------
extern "C" void kernel_launch(void* const* d_in, const int* in_sizes, int n_in,
                              void* d_out, int out_size)
{
    const float* x   =(const float*)d_in[0];
    const float* sem =(const float*)d_in[1];
    const float* wa  =(const float*)d_in[2];
    const float* ba  =(const float*)d_in[3];
    const float* wb  =(const float*)d_in[4];
    const float* bb  =(const float*)d_in[5];
    const float* inw =(const float*)d_in[6];
    const float* inb =(const float*)d_in[7];
    const float* w1  =(const float*)d_in[8];
    const float* b1  =(const float*)d_in[9];
    const float* gm1 =(const float*)d_in[10];
    const float* be1 =(const float*)d_in[11];
    const float* w2  =(const float*)d_in[12];
    const float* b2  =(const float*)d_in[13];
    const float* gm2 =(const float*)d_in[14];
    const float* be2 =(const float*)d_in[15];
    const float* w3  =(const float*)d_in[16];
    const float* b3  =(const float*)d_in[17];
    const float* wq  =(const float*)d_in[18];
    const float* bq  =(const float*)d_in[19];
    const float* wk  =(const float*)d_in[20];
    const float* bk  =(const float*)d_in[21];
    const float* wv  =(const float*)d_in[22];
    const float* bv  =(const float*)d_in[23];
    const float* wo  =(const float*)d_in[24];
    const float* bo  =(const float*)d_in[25];
    const float* rescale=(const float*)d_in[26];
    float* out=(float*)d_out;

    cudaFuncSetAttribute(k1, cudaFuncAttributeMaxDynamicSharedMemorySize, 22080*4);
    cudaFuncSetAttribute(k2, cudaFuncAttributeMaxDynamicSharedMemorySize, 22784*4);
    cudaFuncSetAttribute(k3, cudaFuncAttributeMaxDynamicSharedMemorySize, (128*TP+4096)*4);
    cudaFuncSetAttribute(k5, cudaFuncAttributeMaxDynamicSharedMemorySize, 12352*4);

    kprep<<<16,256>>>(wa,ba,wb,bb);
    kfold<<<32,256>>>(inw,inb,wk,bk,wv,bv);
    k1<<<1024,256,22080*4>>>(x,sem);
    k2<<<1024,256,22784*4>>>(x,w1,b1,gm1,be1,w2,b2,gm2,be2,w3,b3,wq,bq);
    k3<<<dim3(128,4),256,(128*TP+4096)*4>>>();
    k4<<<4,256>>>(rescale,wo);
    k5<<<1024,256,12352*4>>>(bo,out);
}

// round 13
// speedup vs baseline: 1.5921x; 1.1618x over previous
#include <cuda_runtime.h>
#include <math.h>

#define NPIX 16384
#define BN   65536   // 4 * 16384

typedef unsigned long long u64;

// ------------ scratch ------------------------------------------------------
__device__ float g_k[64*BN];
__device__ float g_v[64*BN];
__device__ float g_q[64*BN];
__device__ float g_xm[64*BN];
__device__ float g_Gpart[4*128*1024];
__device__ float g_sqp[4*128*64];
__device__ float g_skp[4*128*64];
__device__ float g_weff[4*4096];     // [b][e*64+cp]
__device__ float g_wcat[4096];       // [c][j]
__device__ float g_wik[4096];        // (in_w@wk) [c][o]
__device__ float g_wiv[4096];        // (in_w@wv) [c][o]
__device__ float g_bcat[64];
__device__ float g_bik[64];
__device__ float g_biv[64];

// ------------ f32x2 helpers (k1/k5) -----------------------------------------
__device__ __forceinline__ u64 pack2(float lo, float hi){
    u64 r; asm("mov.b64 %0, {%1,%2};" : "=l"(r) : "f"(lo), "f"(hi)); return r;
}
__device__ __forceinline__ void unpack2(u64 a, float& lo, float& hi){
    asm("mov.b64 {%0,%1}, %2;" : "=f"(lo), "=f"(hi) : "l"(a));
}
__device__ __forceinline__ u64 fma2_(u64 a, u64 b, u64 c){
    u64 d; asm("fma.rn.f32x2 %0, %1, %2, %3;" : "=l"(d) : "l"(a), "l"(b), "l"(c)); return d;
}
__device__ __forceinline__ u64 add2_(u64 a, u64 b){
    u64 d; asm("add.rn.f32x2 %0, %1, %2;" : "=l"(d) : "l"(a), "l"(b)); return d;
}
__device__ __forceinline__ int SWP(int o, int p){
    return (p & 3) | ((((p >> 2) ^ (o >> 2)) & 7) << 2);
}

#define GSTEP64(W, R, RROW, KK) do{ \
    const float2 _wv = *(const float2*)((W)+(KK)*64+2*lane); \
    int _g = (((wrp)^((RROW)>>2))&7)<<2; \
    const ulonglong2 _xa = *(const ulonglong2*)((R)+(RROW)*32+_g); \
    const ulonglong2 _xb = *(const ulonglong2*)((R)+(RROW)*32+_g+2); \
    u64 _w0=pack2(_wv.x,_wv.x), _w1=pack2(_wv.y,_wv.y); \
    acc2[0][0]=fma2_(_xa.x,_w0,acc2[0][0]); acc2[0][1]=fma2_(_xa.y,_w0,acc2[0][1]); acc2[0][2]=fma2_(_xb.x,_w0,acc2[0][2]); acc2[0][3]=fma2_(_xb.y,_w0,acc2[0][3]); \
    acc2[1][0]=fma2_(_xa.x,_w1,acc2[1][0]); acc2[1][1]=fma2_(_xa.y,_w1,acc2[1][1]); acc2[1][2]=fma2_(_xb.x,_w1,acc2[1][2]); acc2[1][3]=fma2_(_xb.y,_w1,acc2[1][3]); \
}while(0)

// ------------ tf32 mma helpers -----------------------------------------------
__device__ __forceinline__ float tf32f(float x){
    unsigned u; asm("cvt.rna.tf32.f32 %0, %1;" : "=r"(u) : "f"(x));
    return __uint_as_float(u);
}
#define MMA_TF32(D, A0,A1,A2,A3, B0,B1) \
    asm volatile("mma.sync.aligned.m16n8k8.row.col.f32.tf32.tf32.f32 " \
        "{%0,%1,%2,%3},{%4,%5,%6,%7},{%8,%9},{%0,%1,%2,%3};" \
        : "+f"(D[0]),"+f"(D[1]),"+f"(D[2]),"+f"(D[3]) \
        : "r"(A0),"r"(A1),"r"(A2),"r"(A3),"r"(B0),"r"(B1))

// ------------ kprep / kfold --------------------------------------------------
__global__ void kprep(const float* wa, const float* ba, const float* wb, const float* bb)
{
    int t = blockIdx.x*256 + threadIdx.x;
    if (t < 4096){
        int c = t>>6, j = t&63;
        float w;
        if (j < 4) w = wa[c*4 + j];
        else { int u=j-4; int kk=u/3; int d=u-kk*3; w = wb[kk*192 + c*3 + d]; }
        g_wcat[t] = w;
    }
    if (t < 64) g_bcat[t] = (t < 4) ? ba[t] : bb[t-4];
}

__global__ void kfold(const float* inw, const float* inb,
                      const float* wk, const float* bk,
                      const float* wv, const float* bv)
{
    int t = blockIdx.x*256 + threadIdx.x;
    int c = (t>>6)&63, o = t&63;
    const float* wx = (t < 4096) ? wk : wv;
    float acc = 0.f;
    #pragma unroll 4
    for (int m=0;m<64;m++) acc = fmaf(inw[c*64+m], wx[m*64+o], acc);
    if (t < 4096) g_wik[c*64+o] = acc;
    else          g_wiv[c*64+o] = acc;
    if (t < 64){
        float a=0.f, b2=0.f;
        for (int m=0;m<64;m++){ a=fmaf(inb[m],wk[m*64+t],a); b2=fmaf(inb[m],wv[m*64+t],b2); }
        g_bik[t] = a + bk[t];
        g_biv[t] = b2 + bv[t];
    }
}

// ------------ k1: feat path -> k, v (champion) -------------------------------
__global__ void __launch_bounds__(256,2)
k1(const float* __restrict__ x, const float* __restrict__ sem)
{
    extern __shared__ float smx[];
    float* s_wcat = smx;
    float* s_wik  = smx + 4096;
    float* s_wiv  = smx + 8192;
    u64*   R1     = (u64*)(smx + 12288);
    u64*   R2     = (u64*)(smx + 16384);
    u64*   Ssem   = (u64*)(smx + 20480);
    float* s_bias = smx + 21888;

    int t = threadIdx.x, lane = t & 31, wrp = t >> 5;
    int gp0 = blockIdx.x*64;
    int b = gp0 >> 14, pb = gp0 & (NPIX-1);
    int xbase = b*64*NPIX + pb;
    int sbase = b*21*NPIX + pb;

    for (int i=t;i<4096;i+=256){ s_wcat[i]=g_wcat[i]; s_wik[i]=g_wik[i]; s_wiv[i]=g_wiv[i]; }
    if (t<64){ s_bias[t]=g_bcat[t]; s_bias[64+t]=g_bik[t]; s_bias[128+t]=g_biv[t]; }
    for (int i=t;i<2048;i+=256){
        int c=i>>5, pr=i&31;
        R1[c*32 + SWP(c,pr)] = pack2(x[xbase + c*NPIX + pr], x[xbase + c*NPIX + 32 + pr]);
    }
    for (int i=t;i<672;i+=256){
        int kk=i>>5, pr=i&31;
        float s0=sem[sbase+kk*NPIX+pr], s1=sem[sbase+kk*NPIX+32+pr];
        Ssem[kk*33+pr]=pack2(s0>0.f?s0:0.f, s1>0.f?s1:0.f);
    }
    __syncthreads();

    u64 acc2[2][4];
    #pragma unroll
    for (int j=0;j<2;j++){ acc2[j][0]=0ull; acc2[j][1]=0ull; acc2[j][2]=0ull; acc2[j][3]=0ull; }
    #pragma unroll 8
    for (int k=0;k<64;k++) GSTEP64(s_wcat, R1, k, k);
    {
        int _g = ((wrp ^ (lane>>1)) & 7) << 2;
        #pragma unroll
        for (int j=0;j<2;j++){
            int o = 2*lane+j;
            int cls = (o<4) ? 0 : ((o-4)/3 + 1);
            u64 bb = pack2(s_bias[o], s_bias[o]);
            #pragma unroll
            for (int p=0;p<4;p++){
                u64 sm = Ssem[cls*33 + 4*wrp + p];
                R2[o*32 + _g + p] = fma2_(sm, acc2[j][p], bb);
            }
        }
    }
    __syncthreads();

    #pragma unroll
    for (int j=0;j<2;j++){ acc2[j][0]=0ull; acc2[j][1]=0ull; acc2[j][2]=0ull; acc2[j][3]=0ull; }
    #pragma unroll 8
    for (int k=0;k<64;k++) GSTEP64(s_wik, R2, k, k);
    {
        int _g = ((wrp ^ (lane>>1)) & 7) << 2;
        #pragma unroll
        for (int j=0;j<2;j++){
            int o = 2*lane+j;
            u64 bb = pack2(s_bias[64+o], s_bias[64+o]);
            #pragma unroll
            for (int p=0;p<4;p++) R1[o*32 + _g + p] = add2_(acc2[j][p], bb);
        }
    }
    __syncthreads();
    for (int idx=t; idx<2048; idx+=256){
        int o=idx>>5, pr=idx&31;
        float lo,hi; unpack2(R1[o*32+SWP(o,pr)], lo, hi);
        g_k[o*BN + gp0 + pr]      = lo;
        g_k[o*BN + gp0 + 32 + pr] = hi;
    }
    #pragma unroll
    for (int j=0;j<2;j++){ acc2[j][0]=0ull; acc2[j][1]=0ull; acc2[j][2]=0ull; acc2[j][3]=0ull; }
    #pragma unroll 8
    for (int k=0;k<64;k++) GSTEP64(s_wiv, R2, k, k);
    __syncthreads();
    {
        int _g = ((wrp ^ (lane>>1)) & 7) << 2;
        #pragma unroll
        for (int j=0;j<2;j++){
            int o = 2*lane+j;
            u64 bb = pack2(s_bias[128+o], s_bias[128+o]);
            #pragma unroll
            for (int p=0;p<4;p++) R1[o*32 + _g + p] = add2_(acc2[j][p], bb);
        }
    }
    __syncthreads();
    for (int idx=t; idx<2048; idx+=256){
        int o=idx>>5, pr=idx&31;
        float lo,hi; unpack2(R1[o*32+SWP(o,pr)], lo, hi);
        g_v[o*BN + gp0 + pr]      = lo;
        g_v[o*BN + gp0 + 32 + pr] = hi;
    }
}

// ------------ k2: tf32 tensor-core LN-MLP -> xm, q (register-LN) --------------
#define XS_ST 68
#define US_ST 132
#define WS_ST 136
#define W3_ST 72

__global__ void __launch_bounds__(256,2)
k2(const float* __restrict__ x,
   const float* __restrict__ w1, const float* __restrict__ b1,
   const float* __restrict__ gm1, const float* __restrict__ be1,
   const float* __restrict__ w2, const float* __restrict__ b2,
   const float* __restrict__ gm2, const float* __restrict__ be2,
   const float* __restrict__ w3, const float* __restrict__ b3,
   const float* __restrict__ wq, const float* __restrict__ bq)
{
    extern __shared__ float smx[];
    float* Xs  = smx;            // 64x68  = 4352
    float* Us  = smx + 4352;     // 64x132 = 8448
    float* Ws  = smx + 12800;    // 64x136 = 8704
    float* s_p = smx + 21504;    // 896
    float* SSs = smx + 22400;    // 2x64
    float* SSq = smx + 22528;    // 2x64

    int t = threadIdx.x, lane = t&31, wrp = t>>5;
    int gid = lane>>2, tid = lane&3;
    int px0 = (wrp&3)*16, oA = (wrp>>2)*64, oB = (wrp>>2)*32, hh = wrp>>2;
    int r0 = px0+gid, r1 = r0+8;
    int gp0 = blockIdx.x*64;
    int b = gp0>>14, pb = gp0 & (NPIX-1);
    int xbase = b*64*NPIX + pb;

    if (t<128){ s_p[t]=b1[t]; s_p[128+t]=gm1[t]; s_p[256+t]=be1[t];
                s_p[384+t]=b2[t]; s_p[512+t]=gm2[t]; s_p[640+t]=be2[t]; }
    if (t<64){ s_p[768+t]=b3[t]; s_p[832+t]=bq[t]; }
    for (int i=t;i<4096;i+=256){
        int c=i>>6, px=i&63;
        Xs[px*XS_ST+c] = tf32f(x[xbase + c*NPIX + px]);
    }
    for (int i=4*t;i<8192;i+=1024){
        float4 wv = *(const float4*)(w1+i);
        wv.x=tf32f(wv.x); wv.y=tf32f(wv.y); wv.z=tf32f(wv.z); wv.w=tf32f(wv.w);
        *(float4*)&Ws[(i>>7)*WS_ST + (i&127)] = wv;
    }
    __syncthreads();

    // ---- GEMM1: u1 = x @ w1 + b1 (regs) ----
    float D[8][4];
    #pragma unroll
    for (int nb=0;nb<8;nb++){ D[nb][0]=0.f; D[nb][1]=0.f; D[nb][2]=0.f; D[nb][3]=0.f; }
    {
        unsigned a[8][4];
        const float* A0 = Xs + r0*XS_ST + tid;
        const float* A1 = A0 + 8*XS_ST;
        #pragma unroll
        for (int kg=0;kg<8;kg++){
            a[kg][0]=__float_as_uint(A0[kg*8]);
            a[kg][1]=__float_as_uint(A1[kg*8]);
            a[kg][2]=__float_as_uint(A0[kg*8+4]);
            a[kg][3]=__float_as_uint(A1[kg*8+4]);
        }
        #pragma unroll
        for (int nb=0;nb<8;nb++){
            const float* Bp = Ws + tid*WS_ST + oA + nb*8 + gid;
            #pragma unroll
            for (int kg=0;kg<8;kg++){
                unsigned b0=__float_as_uint(Bp[kg*8*WS_ST]);
                unsigned b1=__float_as_uint(Bp[kg*8*WS_ST + 4*WS_ST]);
                MMA_TF32(D[nb], a[kg][0],a[kg][1],a[kg][2],a[kg][3], b0,b1);
            }
        }
    }
    // bias + register LN1 stats
    {
        float s0=0.f,s1=0.f,q0=0.f,q1=0.f;
        #pragma unroll
        for (int nb=0;nb<8;nb++){
            int n0 = oA + nb*8 + 2*tid;
            float bb0=s_p[n0], bb1=s_p[n0+1];
            D[nb][0]+=bb0; D[nb][1]+=bb1; D[nb][2]+=bb0; D[nb][3]+=bb1;
            s0+=D[nb][0]+D[nb][1]; q0=fmaf(D[nb][0],D[nb][0],q0); q0=fmaf(D[nb][1],D[nb][1],q0);
            s1+=D[nb][2]+D[nb][3]; q1=fmaf(D[nb][2],D[nb][2],q1); q1=fmaf(D[nb][3],D[nb][3],q1);
        }
        s0+=__shfl_xor_sync(0xffffffffu,s0,1); s0+=__shfl_xor_sync(0xffffffffu,s0,2);
        s1+=__shfl_xor_sync(0xffffffffu,s1,1); s1+=__shfl_xor_sync(0xffffffffu,s1,2);
        q0+=__shfl_xor_sync(0xffffffffu,q0,1); q0+=__shfl_xor_sync(0xffffffffu,q0,2);
        q1+=__shfl_xor_sync(0xffffffffu,q1,1); q1+=__shfl_xor_sync(0xffffffffu,q1,2);
        if (tid==0){ SSs[hh*64+r0]=s0; SSs[hh*64+r1]=s1; SSq[hh*64+r0]=q0; SSq[hh*64+r1]=q1; }
    }
    __syncthreads();
    // stage w2 half0 while normalizing
    for (int i=4*t;i<8192;i+=1024){
        float4 wv = *(const float4*)(w2+i);
        wv.x=tf32f(wv.x); wv.y=tf32f(wv.y); wv.z=tf32f(wv.z); wv.w=tf32f(wv.w);
        *(float4*)&Ws[(i>>7)*WS_ST + (i&127)] = wv;
    }
    {
        float m0=(SSs[r0]+SSs[64+r0])*(1.f/128.f);
        float m1=(SSs[r1]+SSs[64+r1])*(1.f/128.f);
        float ri0=rsqrtf((SSq[r0]+SSq[64+r0])*(1.f/128.f)-m0*m0+1e-5f);
        float ri1=rsqrtf((SSq[r1]+SSq[64+r1])*(1.f/128.f)-m1*m1+1e-5f);
        #pragma unroll
        for (int nb=0;nb<8;nb++){
            int n0 = oA + nb*8 + 2*tid;
            float g0=s_p[128+n0], g1=s_p[128+n0+1], e0=s_p[256+n0], e1=s_p[256+n0+1];
            float h00=(D[nb][0]-m0)*ri0*g0+e0; h00=h00>0.f?h00:0.01f*h00;
            float h01=(D[nb][1]-m0)*ri0*g1+e1; h01=h01>0.f?h01:0.01f*h01;
            float h10=(D[nb][2]-m1)*ri1*g0+e0; h10=h10>0.f?h10:0.01f*h10;
            float h11=(D[nb][3]-m1)*ri1*g1+e1; h11=h11>0.f?h11:0.01f*h11;
            *(float2*)&Us[r0*US_ST+n0] = make_float2(tf32f(h00), tf32f(h01));
            *(float2*)&Us[r1*US_ST+n0] = make_float2(tf32f(h10), tf32f(h11));
        }
    }
    __syncthreads();

    // ---- GEMM2: u2 = h1 @ w2 + b2 (K=128, two halves) ----
    #pragma unroll
    for (int nb=0;nb<8;nb++){ D[nb][0]=0.f; D[nb][1]=0.f; D[nb][2]=0.f; D[nb][3]=0.f; }
    {
        unsigned a[8][4];
        const float* A0 = Us + r0*US_ST + tid;
        const float* A1 = A0 + 8*US_ST;
        #pragma unroll
        for (int kg=0;kg<8;kg++){
            a[kg][0]=__float_as_uint(A0[kg*8]);
            a[kg][1]=__float_as_uint(A1[kg*8]);
            a[kg][2]=__float_as_uint(A0[kg*8+4]);
            a[kg][3]=__float_as_uint(A1[kg*8+4]);
        }
        #pragma unroll
        for (int nb=0;nb<8;nb++){
            const float* Bp = Ws + tid*WS_ST + oA + nb*8 + gid;
            #pragma unroll
            for (int kg=0;kg<8;kg++){
                unsigned b0=__float_as_uint(Bp[kg*8*WS_ST]);
                unsigned b1=__float_as_uint(Bp[kg*8*WS_ST+4*WS_ST]);
                MMA_TF32(D[nb], a[kg][0],a[kg][1],a[kg][2],a[kg][3], b0,b1);
            }
        }
    }
    __syncthreads();
    for (int i=4*t;i<8192;i+=1024){
        float4 wv = *(const float4*)(w2+8192+i);
        wv.x=tf32f(wv.x); wv.y=tf32f(wv.y); wv.z=tf32f(wv.z); wv.w=tf32f(wv.w);
        *(float4*)&Ws[(i>>7)*WS_ST + (i&127)] = wv;
    }
    __syncthreads();
    {
        unsigned a[8][4];
        const float* A0 = Us + r0*US_ST + 64 + tid;
        const float* A1 = A0 + 8*US_ST;
        #pragma unroll
        for (int kg=0;kg<8;kg++){
            a[kg][0]=__float_as_uint(A0[kg*8]);
            a[kg][1]=__float_as_uint(A1[kg*8]);
            a[kg][2]=__float_as_uint(A0[kg*8+4]);
            a[kg][3]=__float_as_uint(A1[kg*8+4]);
        }
        #pragma unroll
        for (int nb=0;nb<8;nb++){
            const float* Bp = Ws + tid*WS_ST + oA + nb*8 + gid;
            #pragma unroll
            for (int kg=0;kg<8;kg++){
                unsigned b0=__float_as_uint(Bp[kg*8*WS_ST]);
                unsigned b1=__float_as_uint(Bp[kg*8*WS_ST+4*WS_ST]);
                MMA_TF32(D[nb], a[kg][0],a[kg][1],a[kg][2],a[kg][3], b0,b1);
            }
        }
    }
    // bias + register LN2
    {
        float s0=0.f,s1=0.f,q0=0.f,q1=0.f;
        #pragma unroll
        for (int nb=0;nb<8;nb++){
            int n0 = oA + nb*8 + 2*tid;
            float bb0=s_p[384+n0], bb1=s_p[384+n0+1];
            D[nb][0]+=bb0; D[nb][1]+=bb1; D[nb][2]+=bb0; D[nb][3]+=bb1;
            s0+=D[nb][0]+D[nb][1]; q0=fmaf(D[nb][0],D[nb][0],q0); q0=fmaf(D[nb][1],D[nb][1],q0);
            s1+=D[nb][2]+D[nb][3]; q1=fmaf(D[nb][2],D[nb][2],q1); q1=fmaf(D[nb][3],D[nb][3],q1);
        }
        s0+=__shfl_xor_sync(0xffffffffu,s0,1); s0+=__shfl_xor_sync(0xffffffffu,s0,2);
        s1+=__shfl_xor_sync(0xffffffffu,s1,1); s1+=__shfl_xor_sync(0xffffffffu,s1,2);
        q0+=__shfl_xor_sync(0xffffffffu,q0,1); q0+=__shfl_xor_sync(0xffffffffu,q0,2);
        q1+=__shfl_xor_sync(0xffffffffu,q1,1); q1+=__shfl_xor_sync(0xffffffffu,q1,2);
        if (tid==0){ SSs[hh*64+r0]=s0; SSs[hh*64+r1]=s1; SSq[hh*64+r0]=q0; SSq[hh*64+r1]=q1; }
    }
    __syncthreads();
    // stage w3 half0 while normalizing
    for (int i=4*t;i<4096;i+=1024){
        float4 wv = *(const float4*)(w3+i);
        wv.x=tf32f(wv.x); wv.y=tf32f(wv.y); wv.z=tf32f(wv.z); wv.w=tf32f(wv.w);
        *(float4*)&Ws[(i>>6)*W3_ST + (i&63)] = wv;
    }
    {
        float m0=(SSs[r0]+SSs[64+r0])*(1.f/128.f);
        float m1=(SSs[r1]+SSs[64+r1])*(1.f/128.f);
        float ri0=rsqrtf((SSq[r0]+SSq[64+r0])*(1.f/128.f)-m0*m0+1e-5f);
        float ri1=rsqrtf((SSq[r1]+SSq[64+r1])*(1.f/128.f)-m1*m1+1e-5f);
        #pragma unroll
        for (int nb=0;nb<8;nb++){
            int n0 = oA + nb*8 + 2*tid;
            float g0=s_p[512+n0], g1=s_p[512+n0+1], e0=s_p[640+n0], e1=s_p[640+n0+1];
            float h00=(D[nb][0]-m0)*ri0*g0+e0; h00=h00>0.f?h00:0.01f*h00;
            float h01=(D[nb][1]-m0)*ri0*g1+e1; h01=h01>0.f?h01:0.01f*h01;
            float h10=(D[nb][2]-m1)*ri1*g0+e0; h10=h10>0.f?h10:0.01f*h10;
            float h11=(D[nb][3]-m1)*ri1*g1+e1; h11=h11>0.f?h11:0.01f*h11;
            *(float2*)&Us[r0*US_ST+n0] = make_float2(tf32f(h00), tf32f(h01));
            *(float2*)&Us[r1*US_ST+n0] = make_float2(tf32f(h10), tf32f(h11));
        }
    }
    __syncthreads();

    // ---- GEMM3: xm = h2 @ w3 + b3 (K=128, N=64) ----
    float D3[4][4];
    #pragma unroll
    for (int nb=0;nb<4;nb++){ D3[nb][0]=0.f; D3[nb][1]=0.f; D3[nb][2]=0.f; D3[nb][3]=0.f; }
    {
        unsigned a[8][4];
        const float* A0 = Us + r0*US_ST + tid;
        const float* A1 = A0 + 8*US_ST;
        #pragma unroll
        for (int kg=0;kg<8;kg++){
            a[kg][0]=__float_as_uint(A0[kg*8]);
            a[kg][1]=__float_as_uint(A1[kg*8]);
            a[kg][2]=__float_as_uint(A0[kg*8+4]);
            a[kg][3]=__float_as_uint(A1[kg*8+4]);
        }
        #pragma unroll
        for (int nb=0;nb<4;nb++){
            const float* Bp = Ws + tid*W3_ST + oB + nb*8 + gid;
            #pragma unroll
            for (int kg=0;kg<8;kg++){
                unsigned b0=__float_as_uint(Bp[kg*8*W3_ST]);
                unsigned b1=__float_as_uint(Bp[kg*8*W3_ST+4*W3_ST]);
                MMA_TF32(D3[nb], a[kg][0],a[kg][1],a[kg][2],a[kg][3], b0,b1);
            }
        }
    }
    __syncthreads();
    for (int i=4*t;i<4096;i+=1024){
        float4 wv = *(const float4*)(w3+4096+i);
        wv.x=tf32f(wv.x); wv.y=tf32f(wv.y); wv.z=tf32f(wv.z); wv.w=tf32f(wv.w);
        *(float4*)&Ws[(i>>6)*W3_ST + (i&63)] = wv;
    }
    __syncthreads();
    {
        unsigned a[8][4];
        const float* A0 = Us + r0*US_ST + 64 + tid;
        const float* A1 = A0 + 8*US_ST;
        #pragma unroll
        for (int kg=0;kg<8;kg++){
            a[kg][0]=__float_as_uint(A0[kg*8]);
            a[kg][1]=__float_as_uint(A1[kg*8]);
            a[kg][2]=__float_as_uint(A0[kg*8+4]);
            a[kg][3]=__float_as_uint(A1[kg*8+4]);
        }
        #pragma unroll
        for (int nb=0;nb<4;nb++){
            const float* Bp = Ws + tid*W3_ST + oB + nb*8 + gid;
            #pragma unroll
            for (int kg=0;kg<8;kg++){
                unsigned b0=__float_as_uint(Bp[kg*8*W3_ST]);
                unsigned b1=__float_as_uint(Bp[kg*8*W3_ST+4*W3_ST]);
                MMA_TF32(D3[nb], a[kg][0],a[kg][1],a[kg][2],a[kg][3], b0,b1);
            }
        }
    }
    // bias + store fp32 xm into Xs
    #pragma unroll
    for (int nb=0;nb<4;nb++){
        int n0 = oB + nb*8 + 2*tid;
        float bb0=s_p[768+n0], bb1=s_p[768+n0+1];
        *(float2*)&Xs[r0*XS_ST+n0] = make_float2(D3[nb][0]+bb0, D3[nb][1]+bb1);
        *(float2*)&Xs[r1*XS_ST+n0] = make_float2(D3[nb][2]+bb0, D3[nb][3]+bb1);
    }
    __syncthreads();
    // sweep: g_xm (fp32, coalesced) + Us tf32 copy for q-GEMM; stage wq
    for (int idx=t; idx<4096; idx+=256){
        int px=idx&63, o=idx>>6;
        float v = Xs[px*XS_ST+o];
        g_xm[o*BN + gp0 + px] = v;
        Us[px*US_ST+o] = tf32f(v);
    }
    for (int i=4*t;i<4096;i+=1024){
        float4 wv = *(const float4*)(wq+i);
        wv.x=tf32f(wv.x); wv.y=tf32f(wv.y); wv.z=tf32f(wv.z); wv.w=tf32f(wv.w);
        *(float4*)&Ws[(i>>6)*W3_ST + (i&63)] = wv;
    }
    __syncthreads();

    // ---- q-GEMM: q = xm @ wq + bq ----
    float Dq[4][4];
    #pragma unroll
    for (int nb=0;nb<4;nb++){ Dq[nb][0]=0.f; Dq[nb][1]=0.f; Dq[nb][2]=0.f; Dq[nb][3]=0.f; }
    {
        unsigned a[8][4];
        const float* A0 = Us + r0*US_ST + tid;
        const float* A1 = A0 + 8*US_ST;
        #pragma unroll
        for (int kg=0;kg<8;kg++){
            a[kg][0]=__float_as_uint(A0[kg*8]);
            a[kg][1]=__float_as_uint(A1[kg*8]);
            a[kg][2]=__float_as_uint(A0[kg*8+4]);
            a[kg][3]=__float_as_uint(A1[kg*8+4]);
        }
        #pragma unroll
        for (int nb=0;nb<4;nb++){
            const float* Bp = Ws + tid*W3_ST + oB + nb*8 + gid;
            #pragma unroll
            for (int kg=0;kg<8;kg++){
                unsigned b0=__float_as_uint(Bp[kg*8*W3_ST]);
                unsigned b1=__float_as_uint(Bp[kg*8*W3_ST+4*W3_ST]);
                MMA_TF32(Dq[nb], a[kg][0],a[kg][1],a[kg][2],a[kg][3], b0,b1);
            }
        }
    }
    #pragma unroll
    for (int nb=0;nb<4;nb++){
        int n0 = oB + nb*8 + 2*tid;
        float bb0=s_p[832+n0], bb1=s_p[832+n0+1];
        *(float2*)&Xs[r0*XS_ST+n0] = make_float2(Dq[nb][0]+bb0, Dq[nb][1]+bb1);
        *(float2*)&Xs[r1*XS_ST+n0] = make_float2(Dq[nb][2]+bb0, Dq[nb][3]+bb1);
    }
    __syncthreads();
    for (int idx=t; idx<4096; idx+=256){
        int px=idx&63, o=idx>>6;
        g_q[o*BN + gp0 + px] = Xs[px*XS_ST+o];
    }
}

// ------------ k3: Gram + norm partials per 128-pixel chunk -------------------
#define CHUNK 128
#define TP 129
__global__ void __launch_bounds__(256,2) k3()
{
    extern __shared__ float smx[];
    float* qs  = smx;
    float* ks  = smx + 64*TP;
    float* red = smx + 128*TP;
    int t = threadIdx.x;
    int chunk = blockIdx.x, b = blockIdx.y;
    int pbase = b*NPIX + chunk*CHUNK;
    for (int i=t; i<64*CHUNK; i+=256){
        int ch=i>>7, pp=i&(CHUNK-1);
        qs[ch*TP+pp]=g_q[ch*BN+pbase+pp];
        ks[ch*TP+pp]=g_k[ch*BN+pbase+pp];
    }
    __syncthreads();
    int sub=t>>6, combo=t&63;
    int h=combo>>4, d4=(combo>>2)&3, e4=combo&3;
    const float* qsb=qs+(h*16+d4*4)*TP;
    const float* ksb=ks+(h*16+e4*4)*TP;
    float acc[4][4];
    #pragma unroll
    for (int i=0;i<4;i++)
        #pragma unroll
        for (int j=0;j<4;j++) acc[i][j]=0.f;
    for (int pp=sub*32; pp<sub*32+32; pp++){
        float q0=qsb[pp],q1=qsb[TP+pp],q2=qsb[2*TP+pp],q3=qsb[3*TP+pp];
        float k0=ksb[pp],k1v=ksb[TP+pp],k2v=ksb[2*TP+pp],k3v=ksb[3*TP+pp];
        acc[0][0]=fmaf(q0,k0,acc[0][0]); acc[0][1]=fmaf(q0,k1v,acc[0][1]); acc[0][2]=fmaf(q0,k2v,acc[0][2]); acc[0][3]=fmaf(q0,k3v,acc[0][3]);
        acc[1][0]=fmaf(q1,k0,acc[1][0]); acc[1][1]=fmaf(q1,k1v,acc[1][1]); acc[1][2]=fmaf(q1,k2v,acc[1][2]); acc[1][3]=fmaf(q1,k3v,acc[1][3]);
        acc[2][0]=fmaf(q2,k0,acc[2][0]); acc[2][1]=fmaf(q2,k1v,acc[2][1]); acc[2][2]=fmaf(q2,k2v,acc[2][2]); acc[2][3]=fmaf(q2,k3v,acc[2][3]);
        acc[3][0]=fmaf(q3,k0,acc[3][0]); acc[3][1]=fmaf(q3,k1v,acc[3][1]); acc[3][2]=fmaf(q3,k2v,acc[3][2]); acc[3][3]=fmaf(q3,k3v,acc[3][3]);
    }
    #pragma unroll
    for (int i=0;i<4;i++)
        #pragma unroll
        for (int j=0;j<4;j++)
            red[sub*1024 + (h*16+d4*4+i)*16 + (e4*4+j)] = acc[i][j];
    if (t < 64){
        const float* qr=qs+t*TP;
        float a0=0,a1=0,a2=0,a3=0;
        for (int pp=0;pp<CHUNK;pp+=4){
            a0=fmaf(qr[pp+0],qr[pp+0],a0); a1=fmaf(qr[pp+1],qr[pp+1],a1);
            a2=fmaf(qr[pp+2],qr[pp+2],a2); a3=fmaf(qr[pp+3],qr[pp+3],a3);
        }
        g_sqp[(b*128+chunk)*64+t]=(a0+a1)+(a2+a3);
    } else if (t < 128){
        int ch=t-64;
        const float* kr=ks+ch*TP;
        float a0=0,a1=0,a2=0,a3=0;
        for (int pp=0;pp<CHUNK;pp+=4){
            a0=fmaf(kr[pp+0],kr[pp+0],a0); a1=fmaf(kr[pp+1],kr[pp+1],a1);
            a2=fmaf(kr[pp+2],kr[pp+2],a2); a3=fmaf(kr[pp+3],kr[pp+3],a3);
        }
        g_skp[(b*128+chunk)*64+ch]=(a0+a1)+(a2+a3);
    }
    __syncthreads();
    float* gout = g_Gpart + (b*128+chunk)*1024;
    for (int idx=t; idx<1024; idx+=256)
        gout[idx] = (red[idx]+red[1024+idx]) + (red[2048+idx]+red[3072+idx]);
}

// ------------ k4: reduce + softmax + fold A into wo --------------------------
__global__ void k4(const float* __restrict__ rescale, const float* __restrict__ wo)
{
    __shared__ float sG[1024];
    __shared__ float snq[64], snk[64];
    __shared__ float sA[1024];
    __shared__ float swo[4096];
    int b=blockIdx.x, t=threadIdx.x;
    {
        float a0=0.f,a1=0.f,a2=0.f,a3=0.f;
        for (int c=0;c<128;c++){
            const float4 v = ((const float4*)(g_Gpart+(b*128+c)*1024))[t];
            a0+=v.x; a1+=v.y; a2+=v.z; a3+=v.w;
        }
        sG[t*4+0]=a0; sG[t*4+1]=a1; sG[t*4+2]=a2; sG[t*4+3]=a3;
    }
    if (t<64){
        float aq=0.f, ak=0.f;
        for (int c=0;c<128;c++){ aq+=g_sqp[(b*128+c)*64+t]; ak+=g_skp[(b*128+c)*64+t]; }
        snq[t]=sqrtf(aq)+1e-8f; snk[t]=sqrtf(ak)+1e-8f;
    }
    for (int i=t;i<4096;i+=256) swo[i]=wo[i];
    __syncthreads();
    if (t<64){
        int h=t>>4;
        float r=rescale[h], nq=snq[t];
        float ev[16]; float mx=-1e30f;
        #pragma unroll
        for (int e=0;e<16;e++){ ev[e]=sG[t*16+e]/(nq*snk[h*16+e])*r; mx=fmaxf(mx,ev[e]); }
        float ss=0.f;
        #pragma unroll
        for (int e=0;e<16;e++){ ev[e]=expf(ev[e]-mx); ss+=ev[e]; }
        float inv=1.f/ss;
        #pragma unroll
        for (int e=0;e<16;e++) sA[t*16+e]=ev[e]*inv;
    }
    __syncthreads();
    for (int idx=t; idx<4096; idx+=256){
        int cp=idx>>6, e=idx&63, h=e>>4, e15=e&15;
        float acc=0.f;
        #pragma unroll
        for (int d=0;d<16;d++)
            acc = fmaf(sA[h*256 + d*16 + e15], swo[(h*16+d)*64 + cp], acc);
        g_weff[b*4096 + e*64 + cp] = acc;
    }
}

// ------------ k5: out = v @ Weff + bo + xm (champion) -------------------------
__global__ void __launch_bounds__(256,4)
k5(const float* __restrict__ bo, float* __restrict__ out)
{
    extern __shared__ float smx[];
    float* s_w = smx;
    u64*   R1  = (u64*)(smx + 4096);
    u64*   R2  = (u64*)(smx + 8192);
    float* sbo = smx + 12288;

    int t = threadIdx.x, lane = t & 31, wrp = t >> 5;
    int gp0 = blockIdx.x*64;
    int b = gp0 >> 14, pb = gp0 & (NPIX-1);

    for (int i=t;i<4096;i+=256) s_w[i]=g_weff[b*4096+i];
    if (t<64) sbo[t]=bo[t];
    for (int i=t;i<2048;i+=256){
        int e=i>>5, pr=i&31;
        R1[e*32 + SWP(e,pr)] = pack2(g_v[e*BN + gp0 + pr], g_v[e*BN + gp0 + 32 + pr]);
    }
    __syncthreads();

    u64 acc2[2][4];
    #pragma unroll
    for (int j=0;j<2;j++){ acc2[j][0]=0ull; acc2[j][1]=0ull; acc2[j][2]=0ull; acc2[j][3]=0ull; }
    #pragma unroll 8
    for (int k=0;k<64;k++) GSTEP64(s_w, R1, k, k);
    {
        int _g = ((wrp ^ (lane>>1)) & 7) << 2;
        #pragma unroll
        for (int j=0;j<2;j++){
            int o = 2*lane+j;
            #pragma unroll
            for (int p=0;p<4;p++) R2[o*32 + _g + p] = acc2[j][p];
        }
    }
    __syncthreads();
    for (int idx=t; idx<2048; idx+=256){
        int o=idx>>5, pr=idx&31;
        float lo,hi; unpack2(R2[o*32+SWP(o,pr)], lo, hi);
        size_t row = (size_t)(b*64+o)*NPIX;
        out[row + pb + pr]      = lo + sbo[o] + g_xm[o*BN + gp0 + pr];
        out[row + pb + 32 + pr] = hi + sbo[o] + g_xm[o*BN + gp0 + 32 + pr];
    }
}

// ------------ launch ----------------------------------------------------------
extern "C" void kernel_launch(void* const* d_in, const int* in_sizes, int n_in,
                              void* d_out, int out_size)
{
    const float* x   =(const float*)d_in[0];
    const float* sem =(const float*)d_in[1];
    const float* wa  =(const float*)d_in[2];
    const float* ba  =(const float*)d_in[3];
    const float* wb  =(const float*)d_in[4];
    const float* bb  =(const float*)d_in[5];
    const float* inw =(const float*)d_in[6];
    const float* inb =(const float*)d_in[7];
    const float* w1  =(const float*)d_in[8];
    const float* b1  =(const float*)d_in[9];
    const float* gm1 =(const float*)d_in[10];
    const float* be1 =(const float*)d_in[11];
    const float* w2  =(const float*)d_in[12];
    const float* b2  =(const float*)d_in[13];
    const float* gm2 =(const float*)d_in[14];
    const float* be2 =(const float*)d_in[15];
    const float* w3  =(const float*)d_in[16];
    const float* b3  =(const float*)d_in[17];
    const float* wq  =(const float*)d_in[18];
    const float* bq  =(const float*)d_in[19];
    const float* wk  =(const float*)d_in[20];
    const float* bk  =(const float*)d_in[21];
    const float* wv  =(const float*)d_in[22];
    const float* bv  =(const float*)d_in[23];
    const float* wo  =(const float*)d_in[24];
    const float* bo  =(const float*)d_in[25];
    const float* rescale=(const float*)d_in[26];
    float* out=(float*)d_out;

    cudaFuncSetAttribute(k1, cudaFuncAttributeMaxDynamicSharedMemorySize, 22080*4);
    cudaFuncSetAttribute(k2, cudaFuncAttributeMaxDynamicSharedMemorySize, 22656*4);
    cudaFuncSetAttribute(k3, cudaFuncAttributeMaxDynamicSharedMemorySize, (128*TP+4096)*4);
    cudaFuncSetAttribute(k5, cudaFuncAttributeMaxDynamicSharedMemorySize, 12352*4);

    kprep<<<16,256>>>(wa,ba,wb,bb);
    kfold<<<32,256>>>(inw,inb,wk,bk,wv,bv);
    k1<<<1024,256,22080*4>>>(x,sem);
    k2<<<1024,256,22656*4>>>(x,w1,b1,gm1,be1,w2,b2,gm2,be2,w3,b3,wq,bq);
    k3<<<dim3(128,4),256,(128*TP+4096)*4>>>();
    k4<<<4,256>>>(rescale,wo);
    k5<<<1024,256,12352*4>>>(bo,out);
}